// round 12
// baseline (speedup 1.0000x reference)
#include <cuda_runtime.h>
#include <cuda_fp16.h>
#include <math.h>
#include <stdint.h>

#define BB 4
#define NN 16384
#define DIMM 256
#define HH 8
#define DD 64
#define SS 64
#define INNERR 512

// ---------------- device scratch ----------------
__device__ __half g_xh[(size_t)BB * NN * DIMM];         // x in half
__device__ __half g_CWH[HH * 128 * DIMM];               // combined weight [h][col][k], half
__device__ float  g_Cb[HH * 128];                       // combined bias (fp32)
__device__ __half g_w[(size_t)BB * NN * INNERR];        // softmax slice weights [b][n][j], half
__device__ float  g_tok[BB * HH * SS * DD];             // accumulated tok (atomics)
__device__ float  g_norm[BB * HH * SS];                 // slice_norm (atomics)
__device__ float  g_ot[BB * HH * DD * SS];              // out_tok TRANSPOSED [b][h][d][s]
__device__ __half g_M[BB * DIMM * INNERR];              // M [b][o][j], half

// ---------------- helpers ----------------
__device__ __forceinline__ float tf32r(float f) {
    uint32_t u;
    asm("cvt.rna.tf32.f32 %0, %1;" : "=r"(u) : "f"(f));
    return __uint_as_float(u);
}
__device__ __forceinline__ uint32_t FB(float f) { return __float_as_uint(f); }
__device__ __forceinline__ uint32_t ph2(float a, float b) {
    __half2 h = __floats2half2_rn(a, b);
    return *(uint32_t*)&h;
}
__device__ __forceinline__ void cpa16(void* s, const void* g) {
    uint32_t sa = (uint32_t)__cvta_generic_to_shared(s);
    asm volatile("cp.async.cg.shared.global [%0], [%1], 16;\n" :: "r"(sa), "l"(g));
}
#define CPA_COMMIT asm volatile("cp.async.commit_group;\n" ::: "memory")
#define CPA_WAIT2  asm volatile("cp.async.wait_group 2;\n" ::: "memory")
#define CPA_WAIT1  asm volatile("cp.async.wait_group 1;\n" ::: "memory")
#define CPA_WAIT0  asm volatile("cp.async.wait_group 0;\n" ::: "memory")

__device__ __forceinline__ void mmat(float* d, uint32_t a0, uint32_t a1, uint32_t a2, uint32_t a3,
                                     uint32_t b0, uint32_t b1) {
    asm volatile(
        "mma.sync.aligned.m16n8k8.row.col.f32.tf32.tf32.f32 "
        "{%0,%1,%2,%3},{%4,%5,%6,%7},{%8,%9},{%0,%1,%2,%3};"
        : "+f"(d[0]), "+f"(d[1]), "+f"(d[2]), "+f"(d[3])
        : "r"(a0), "r"(a1), "r"(a2), "r"(a3), "r"(b0), "r"(b1));
}

__device__ __forceinline__ void mmah(float* d, uint32_t a0, uint32_t a1, uint32_t a2, uint32_t a3,
                                     uint32_t b0, uint32_t b1) {
    asm volatile(
        "mma.sync.aligned.m16n8k16.row.col.f32.f16.f16.f32 "
        "{%0,%1,%2,%3},{%4,%5,%6,%7},{%8,%9},{%0,%1,%2,%3};"
        : "+f"(d[0]), "+f"(d[1]), "+f"(d[2]), "+f"(d[3])
        : "r"(a0), "r"(a1), "r"(a2), "r"(a3), "r"(b0), "r"(b1));
}

// ---------------- x -> half ----------------
__global__ void k_conv(const float* __restrict__ x) {
    size_t i = ((size_t)blockIdx.x * 256 + threadIdx.x) * 8;
    float4 a = *(const float4*)(x + i);
    float4 b = *(const float4*)(x + i + 4);
    uint4 p;
    p.x = ph2(a.x, a.y); p.y = ph2(a.z, a.w);
    p.z = ph2(b.x, b.y); p.w = ph2(b.z, b.w);
    *(uint4*)(g_xh + i) = p;
}

// ---------------- prep ----------------
__global__ void k_prep(const float* __restrict__ Wx, const float* __restrict__ bx,
                       const float* __restrict__ Wfx, const float* __restrict__ bfx,
                       const float* __restrict__ Wslice, const float* __restrict__ bslice,
                       const float* __restrict__ temperature) {
    int h = blockIdx.x;
    int k = blockIdx.y;
    int col = threadIdx.x;

    int gid = (h * 256 + k) * 128 + col;
    if (gid < BB * HH * SS * DD) g_tok[gid] = 0.f;
    if (gid < BB * HH * SS) g_norm[gid] = 0.f;

    float invt = 1.f / fmaxf(temperature[h], 1e-4f);
    float v;
    if (col < 64) {
        v = Wfx[(h * 64 + col) * DIMM + k];
    } else {
        int s = col - 64;
        float acc = 0.f;
        #pragma unroll 8
        for (int d = 0; d < 64; d++)
            acc += Wslice[s * 64 + d] * Wx[(h * 64 + d) * DIMM + k];
        v = acc * invt;
    }
    g_CWH[(h * 128 + col) * DIMM + k] = __float2half_rn(v);
    if (k == 0) {
        float bv;
        if (col < 64) {
            bv = bfx[h * 64 + col];
        } else {
            int s = col - 64;
            float acc = bslice[s];
            #pragma unroll 8
            for (int d = 0; d < 64; d++) acc += Wslice[s * 64 + d] * bx[h * 64 + d];
            bv = acc * invt;
        }
        g_Cb[h * 128 + col] = bv;
    }
}

// ---------------- pass 1: 3-stage pipelined fp16 mma + softmax + tok ----------------
// grid (H, N/128, B), block 256, dyn smem = 110592 B (3 stages of 36864)
__global__ __launch_bounds__(256, 2) void k1() {
    extern __shared__ float sm[];
    __half* base = (__half*)sm;
    const int h = blockIdx.x, nt = blockIdx.y, b = blockIdx.z;
    const int tid = threadIdx.x;
    const int lane = tid & 31, wid = tid >> 5;
    const int wm = wid & 3, wn = wid >> 2;
    const int g = lane >> 2, k4 = lane & 3;
    const int n0 = nt * 128;

    const __half* xh = g_xh + (size_t)(b * NN + n0) * DIMM;
    const __half* cw = g_CWH + h * 128 * DIMM;

    float acc[16][4];
    #pragma unroll
    for (int i = 0; i < 16; i++)
        #pragma unroll
        for (int j = 0; j < 4; j++) acc[i][j] = 0.f;

    auto issue = [&](int c) {
        __half* xs = base + (c % 3) * 18432;
        __half* ws = xs + 9216;
        int kc = c * 64;
        for (int i = tid; i < 1024; i += 256) {
            int t = i >> 3, v8 = i & 7;
            cpa16(xs + t * 72 + v8 * 8, xh + (size_t)t * DIMM + kc + v8 * 8);
            cpa16(ws + t * 72 + v8 * 8, cw + (size_t)t * DIMM + kc + v8 * 8);
        }
        CPA_COMMIT;
    };

    issue(0); issue(1);
    for (int c = 0; c < 4; c++) {
        if (c + 2 < 4) { issue(c + 2); CPA_WAIT2; }
        else if (c + 1 < 4) { CPA_WAIT1; }
        else { CPA_WAIT0; }
        __syncthreads();
        __half* xs = base + (c % 3) * 18432;
        __half* ws = xs + 9216;
        #pragma unroll
        for (int ks = 0; ks < 4; ks++) {
            const int kb = ks * 16;
            uint32_t A[2][4];
            #pragma unroll
            for (int mi = 0; mi < 2; mi++) {
                int r = wm * 32 + mi * 16 + g;
                const __half* x0 = xs + r * 72 + kb;
                const __half* x1 = xs + (r + 8) * 72 + kb;
                A[mi][0] = *(const uint32_t*)(x0 + 2 * k4);
                A[mi][1] = *(const uint32_t*)(x1 + 2 * k4);
                A[mi][2] = *(const uint32_t*)(x0 + 2 * k4 + 8);
                A[mi][3] = *(const uint32_t*)(x1 + 2 * k4 + 8);
            }
            #pragma unroll
            for (int ni = 0; ni < 8; ni++) {
                int cc = wn * 64 + ni * 8 + g;
                const __half* bp = ws + cc * 72 + kb;
                uint32_t B0 = *(const uint32_t*)(bp + 2 * k4);
                uint32_t B1 = *(const uint32_t*)(bp + 2 * k4 + 8);
                mmah(acc[0 * 8 + ni], A[0][0], A[0][1], A[0][2], A[0][3], B0, B1);
                mmah(acc[1 * 8 + ni], A[1][0], A[1][1], A[1][2], A[1][3], B0, B1);
            }
        }
        __syncthreads();
    }

    // epilogue: bias + stage fx (tf32-rounded fp32) and logits (fp32)
    float* fxs = sm;                 // [128][72]
    float* lgs = sm + 128 * 72;      // [128][72]
    {
        const float* cb = g_Cb + h * 128;
        float* dst = wn ? lgs : fxs;
        #pragma unroll
        for (int mi = 0; mi < 2; mi++) {
            int r0 = wm * 32 + mi * 16 + g;
            #pragma unroll
            for (int ni = 0; ni < 8; ni++) {
                int cl = ni * 8 + k4 * 2;
                float b0 = cb[wn * 64 + cl], b1 = cb[wn * 64 + cl + 1];
                float v00 = acc[mi * 8 + ni][0] + b0, v01 = acc[mi * 8 + ni][1] + b1;
                float v10 = acc[mi * 8 + ni][2] + b0, v11 = acc[mi * 8 + ni][3] + b1;
                if (!wn) { v00 = tf32r(v00); v01 = tf32r(v01); v10 = tf32r(v10); v11 = tf32r(v11); }
                dst[r0 * 72 + cl] = v00;
                dst[r0 * 72 + cl + 1] = v01;
                dst[(r0 + 8) * 72 + cl] = v10;
                dst[(r0 + 8) * 72 + cl + 1] = v11;
            }
        }
    }
    __syncthreads();

    // softmax: 128 tokens, 2 threads/token; write g_w as half
    {
        int tok = tid >> 1, q2 = tid & 1;
        float* row = lgs + tok * 72 + q2 * 32;
        float m = -1e30f;
        #pragma unroll
        for (int s = 0; s < 32; s++) m = fmaxf(m, row[s]);
        m = fmaxf(m, __shfl_xor_sync(0xffffffffu, m, 1));
        float e[32];
        float sum = 0.f;
        #pragma unroll
        for (int s = 0; s < 32; s++) { e[s] = __expf(row[s] - m); sum += e[s]; }
        sum += __shfl_xor_sync(0xffffffffu, sum, 1);
        float inv = 1.f / sum;
        float v[32];
        #pragma unroll
        for (int s = 0; s < 32; s++) { v[s] = e[s] * inv; row[s] = tf32r(v[s]); }
        __half* gw = g_w + (size_t)(b * NN + n0 + tok) * INNERR + h * 64 + q2 * 32;
        uint4* gp = (uint4*)gw;
        gp[0] = make_uint4(ph2(v[0], v[1]), ph2(v[2], v[3]), ph2(v[4], v[5]), ph2(v[6], v[7]));
        gp[1] = make_uint4(ph2(v[8], v[9]), ph2(v[10], v[11]), ph2(v[12], v[13]), ph2(v[14], v[15]));
        gp[2] = make_uint4(ph2(v[16], v[17]), ph2(v[18], v[19]), ph2(v[20], v[21]), ph2(v[22], v[23]));
        gp[3] = make_uint4(ph2(v[24], v[25]), ph2(v[26], v[27]), ph2(v[28], v[29]), ph2(v[30], v[31]));
    }
    __syncthreads();

    // slice_norm
    if (tid < 64) {
        float ns = 0.f;
        #pragma unroll 8
        for (int t = 0; t < 128; t++) ns += lgs[t * 72 + tid];
        atomicAdd(&g_norm[((size_t)b * HH + h) * 64 + tid], ns);
    }

    // tok[s][d] += sum_t w[t][s] * fx[t][d]  (tf32 mma)
    {
        float a2[4][4];
        #pragma unroll
        for (int i = 0; i < 4; i++)
            #pragma unroll
            for (int j = 0; j < 4; j++) a2[i][j] = 0.f;
        const int m0 = (wid & 3) * 16;
        const int dh = (wid >> 2) * 32;
        #pragma unroll
        for (int ks = 0; ks < 16; ks++) {
            const int kb = ks * 8;
            uint32_t A0 = FB(lgs[(kb + k4) * 72 + m0 + g]);
            uint32_t A1 = FB(lgs[(kb + k4) * 72 + m0 + g + 8]);
            uint32_t A2 = FB(lgs[(kb + k4 + 4) * 72 + m0 + g]);
            uint32_t A3 = FB(lgs[(kb + k4 + 4) * 72 + m0 + g + 8]);
            #pragma unroll
            for (int ni = 0; ni < 4; ni++) {
                int c = dh + ni * 8 + g;
                uint32_t B0 = FB(fxs[(kb + k4) * 72 + c]);
                uint32_t B1 = FB(fxs[(kb + k4 + 4) * 72 + c]);
                mmat(a2[ni], A0, A1, A2, A3, B0, B1);
            }
        }
        float* gt = g_tok + (size_t)((b * HH + h) * 64) * 64;
        #pragma unroll
        for (int ni = 0; ni < 4; ni++) {
            int s0 = m0 + g, c0 = dh + ni * 8 + k4 * 2;
            atomicAdd(gt + s0 * 64 + c0,           a2[ni][0]);
            atomicAdd(gt + s0 * 64 + c0 + 1,       a2[ni][1]);
            atomicAdd(gt + (s0 + 8) * 64 + c0,     a2[ni][2]);
            atomicAdd(gt + (s0 + 8) * 64 + c0 + 1, a2[ni][3]);
        }
    }
}

// ---------------- k2: cross-slice attention only (writes g_ot transposed) ----------------
__device__ __forceinline__ void gemm16(const float* __restrict__ A, int sa,
                                       const float* __restrict__ B /* stride 68 */,
                                       int tr, int tc, float o[4][4]) {
    #pragma unroll
    for (int i = 0; i < 4; i++)
        #pragma unroll
        for (int j = 0; j < 4; j++) o[i][j] = 0.f;
    #pragma unroll 4
    for (int e = 0; e < 64; e++) {
        float4 bv = *(const float4*)(B + e * 68 + tc * 4);
        #pragma unroll
        for (int i = 0; i < 4; i++) {
            float a = A[(tr * 4 + i) * sa + e];
            o[i][0] += a * bv.x; o[i][1] += a * bv.y;
            o[i][2] += a * bv.z; o[i][3] += a * bv.w;
        }
    }
}

// grid (H, B), block 256, dyn smem = 156160 B
__global__ void k2(const float* __restrict__ Wq, const float* __restrict__ Wk,
                   const float* __restrict__ Wv, const float* __restrict__ ascale_p,
                   const float* __restrict__ srs_p) {
    extern __shared__ float sm[];
    float* rn   = sm;                    // [512]
    float* tokn = sm + 512;              // [64][65]
    float* kv   = sm + 4672;             // [64][65]
    float* wq   = sm + 8832;             // [64][68] transposed [e][d]
    float* wk   = sm + 13184;            // [64][68]
    float* wv   = sm + 17536;            // [64][68]
    float* qq   = sm + 21888;            // [64][65]
    float* kkt  = sm + 26048;            // [64][68]
    float* vv   = sm + 30400;            // [64][68]
    float* att  = sm + 34752;            // [64][65]
    float* nqi  = sm + 38912;            // [64]
    float* nki  = sm + 38976;            // [64]
    const int h = blockIdx.x, b = blockIdx.y;
    const int tid = threadIdx.x;
    const int tr = tid >> 4, tc = tid & 15;

    for (int i = tid; i < 512; i += 256) rn[i] = __frcp_rn(g_norm[b * 512 + i] + 1e-5f);
    for (int i = tid; i < 4096; i += 256) {
        int e = i & 63, d = i >> 6;
        wq[e * 68 + d] = Wq[d * 64 + e];
        wk[e * 68 + d] = Wk[d * 64 + e];
        wv[e * 68 + d] = Wv[d * 64 + e];
    }
    __syncthreads();

    for (int i = tid; i < 4096; i += 256) {
        int s = i >> 6, d = i & 63;
        float accv = 0.f;
        #pragma unroll
        for (int hh = 0; hh < 8; hh++)
            accv += g_tok[((b * 8 + hh) * 64 + s) * 64 + d] * rn[hh * 64 + s];
        kv[s * 65 + d] = accv * 0.125f;
        tokn[s * 65 + d] = g_tok[((b * 8 + h) * 64 + s) * 64 + d] * rn[h * 64 + s];
    }
    __syncthreads();

    // merged q/k/v GEMMs
    {
        float oq[4][4], ok[4][4], ov[4][4];
        #pragma unroll
        for (int i = 0; i < 4; i++)
            #pragma unroll
            for (int j = 0; j < 4; j++) { oq[i][j] = 0.f; ok[i][j] = 0.f; ov[i][j] = 0.f; }
        #pragma unroll 2
        for (int e = 0; e < 64; e++) {
            float4 bq = *(const float4*)(wq + e * 68 + tc * 4);
            float4 bk = *(const float4*)(wk + e * 68 + tc * 4);
            float4 bv = *(const float4*)(wv + e * 68 + tc * 4);
            #pragma unroll
            for (int i = 0; i < 4; i++) {
                float aq = tokn[(tr * 4 + i) * 65 + e];
                float ak = kv[(tr * 4 + i) * 65 + e];
                oq[i][0] += aq * bq.x; oq[i][1] += aq * bq.y; oq[i][2] += aq * bq.z; oq[i][3] += aq * bq.w;
                ok[i][0] += ak * bk.x; ok[i][1] += ak * bk.y; ok[i][2] += ak * bk.z; ok[i][3] += ak * bk.w;
                ov[i][0] += ak * bv.x; ov[i][1] += ak * bv.y; ov[i][2] += ak * bv.z; ov[i][3] += ak * bv.w;
            }
        }
        #pragma unroll
        for (int i = 0; i < 4; i++)
            #pragma unroll
            for (int j = 0; j < 4; j++) {
                qq[(tr * 4 + i) * 65 + tc * 4 + j]  = oq[i][j];
                kkt[(tc * 4 + j) * 68 + tr * 4 + i] = ok[i][j];
                vv[(tr * 4 + i) * 68 + tc * 4 + j]  = ov[i][j];
            }
    }
    __syncthreads();

    if (tid < 64) {
        float s2 = 0.f;
        #pragma unroll 8
        for (int d = 0; d < 64; d++) { float v = qq[tid * 65 + d]; s2 += v * v; }
        nqi[tid] = rsqrtf(fmaxf(s2, 1e-24f));
    } else if (tid < 128) {
        int s = tid - 64;
        float s2 = 0.f;
        #pragma unroll 8
        for (int d = 0; d < 64; d++) { float v = kkt[d * 68 + s]; s2 += v * v; }
        nki[s] = rsqrtf(fmaxf(s2, 1e-24f));
    }
    __syncthreads();

    float o[4][4];
    gemm16(qq, 65, kkt, tr, tc, o);
    {
        float asc = ascale_p[h];
        float rq[4], rk[4];
        #pragma unroll
        for (int i = 0; i < 4; i++) rq[i] = asc * nqi[tr * 4 + i];
        #pragma unroll
        for (int j = 0; j < 4; j++) rk[j] = nki[tc * 4 + j];
        #pragma unroll
        for (int i = 0; i < 4; i++)
            #pragma unroll
            for (int j = 0; j < 4; j++)
                att[(tr * 4 + i) * 65 + tc * 4 + j] = o[i][j] * rq[i] * rk[j];
    }
    __syncthreads();

    // softmax rows of att
    {
        int gg = tid >> 2, q4 = tid & 3;
        float* row = att + gg * 65;
        float m = -1e30f;
        #pragma unroll
        for (int s = 0; s < 16; s++) m = fmaxf(m, row[q4 * 16 + s]);
        m = fmaxf(m, __shfl_xor_sync(0xffffffffu, m, 1));
        m = fmaxf(m, __shfl_xor_sync(0xffffffffu, m, 2));
        float e[16];
        float sum = 0.f;
        #pragma unroll
        for (int s = 0; s < 16; s++) { e[s] = __expf(row[q4 * 16 + s] - m); sum += e[s]; }
        sum += __shfl_xor_sync(0xffffffffu, sum, 1);
        sum += __shfl_xor_sync(0xffffffffu, sum, 2);
        float inv = 1.f / sum;
        #pragma unroll
        for (int s = 0; s < 16; s++) row[q4 * 16 + s] = e[s] * inv;
    }
    __syncthreads();

    // out_tok = att @ v + sr * tokn -> write g_ot transposed [b][h][d][s]
    gemm16(att, 65, vv, tr, tc, o);
    {
        float sr = srs_p[0];
        float* gb = g_ot + (size_t)((b * 8 + h) * 64) * 64;
        #pragma unroll
        for (int j = 0; j < 4; j++) {
            int d = tc * 4 + j;
            float4 v4;
            v4.x = o[0][j] + sr * tokn[(tr * 4 + 0) * 65 + d];
            v4.y = o[1][j] + sr * tokn[(tr * 4 + 1) * 65 + d];
            v4.z = o[2][j] + sr * tokn[(tr * 4 + 2) * 65 + d];
            v4.w = o[3][j] + sr * tokn[(tr * 4 + 3) * 65 + d];
            *(float4*)(gb + d * 64 + tr * 4) = v4;
        }
    }
}

// ---------------- k2m: M[b][o][h*64+s] = sum_d Wout[o][h*64+d] * ot[b][h][d][s] ----------------
// grid (H, B, 4), block 256
__global__ void k2m(const float* __restrict__ Wout) {
    __shared__ float wos[64 * 68];
    __shared__ float ots[64 * 68];
    const int h = blockIdx.x, b = blockIdx.y, og = blockIdx.z;
    const int o0 = og * 64;
    const int tid = threadIdx.x;

    for (int i = tid; i < 4096; i += 256) {
        int oo = i >> 6, d = i & 63;
        wos[oo * 68 + d] = Wout[(size_t)(o0 + oo) * INNERR + h * 64 + d];
    }
    const float* gb = g_ot + (size_t)((b * 8 + h) * 64) * 64;
    for (int i = tid; i < 4096; i += 256) {
        int d = i >> 6, s = i & 63;
        ots[d * 68 + s] = gb[d * 64 + s];
    }
    __syncthreads();

    const int to = tid >> 2;        // o in [0,64)
    const int ts = tid & 3;         // s block of 16
    float accm[16];
    #pragma unroll
    for (int j = 0; j < 16; j++) accm[j] = 0.f;
    #pragma unroll 4
    for (int d = 0; d < 64; d++) {
        float a = wos[to * 68 + d];
        float4 s0 = *(const float4*)(ots + d * 68 + ts * 16);
        float4 s1 = *(const float4*)(ots + d * 68 + ts * 16 + 4);
        float4 s2 = *(const float4*)(ots + d * 68 + ts * 16 + 8);
        float4 s3 = *(const float4*)(ots + d * 68 + ts * 16 + 12);
        accm[0]  += a * s0.x; accm[1]  += a * s0.y; accm[2]  += a * s0.z; accm[3]  += a * s0.w;
        accm[4]  += a * s1.x; accm[5]  += a * s1.y; accm[6]  += a * s1.z; accm[7]  += a * s1.w;
        accm[8]  += a * s2.x; accm[9]  += a * s2.y; accm[10] += a * s2.z; accm[11] += a * s2.w;
        accm[12] += a * s3.x; accm[13] += a * s3.y; accm[14] += a * s3.z; accm[15] += a * s3.w;
    }
    __half* mp = g_M + ((size_t)(b * DIMM + o0 + to)) * INNERR + h * 64 + ts * 16;
    uint4 p0, p1;
    p0.x = ph2(accm[0], accm[1]);   p0.y = ph2(accm[2], accm[3]);
    p0.z = ph2(accm[4], accm[5]);   p0.w = ph2(accm[6], accm[7]);
    p1.x = ph2(accm[8], accm[9]);   p1.y = ph2(accm[10], accm[11]);
    p1.z = ph2(accm[12], accm[13]); p1.w = ph2(accm[14], accm[15]);
    ((uint4*)mp)[0] = p0;
    ((uint4*)mp)[1] = p1;
}

// ---------------- pass 2: 3-stage pipelined y = w @ M^T + bout ----------------
// grid (2, N/128, B), block 256, dyn smem = 110592 B
__global__ __launch_bounds__(256, 2) void k3(const float* __restrict__ bout, float* __restrict__ out) {
    extern __shared__ float sm[];
    __half* base = (__half*)sm;
    const int cb = blockIdx.x, nt = blockIdx.y, b = blockIdx.z;
    const int tid = threadIdx.x;
    const int lane = tid & 31, wid = tid >> 5;
    const int wm = wid & 3, wn = wid >> 2;
    const int g = lane >> 2, k4 = lane & 3;
    const int n0 = nt * 128, col0 = cb * 128;
    const __half* wp = g_w + (size_t)(b * NN + n0) * INNERR;
    const __half* mp = g_M + (size_t)b * DIMM * INNERR + (size_t)col0 * INNERR;

    float acc[16][4];
    #pragma unroll
    for (int i = 0; i < 16; i++)
        #pragma unroll
        for (int j = 0; j < 4; j++) acc[i][j] = 0.f;

    auto issue = [&](int c) {
        __half* wt = base + (c % 3) * 18432;
        __half* ms = wt + 9216;
        int kc = c * 64;
        for (int i = tid; i < 1024; i += 256) {
            int t = i >> 3, v8 = i & 7;
            cpa16(wt + t * 72 + v8 * 8, wp + (size_t)t * INNERR + kc + v8 * 8);
            cpa16(ms + t * 72 + v8 * 8, mp + (size_t)t * INNERR + kc + v8 * 8);
        }
        CPA_COMMIT;
    };

    issue(0); issue(1);
    for (int c = 0; c < 8; c++) {
        if (c + 2 < 8) { issue(c + 2); CPA_WAIT2; }
        else if (c + 1 < 8) { CPA_WAIT1; }
        else { CPA_WAIT0; }
        __syncthreads();
        __half* wt = base + (c % 3) * 18432;
        __half* ms = wt + 9216;
        #pragma unroll
        for (int ks = 0; ks < 4; ks++) {
            const int kb = ks * 16;
            uint32_t A[2][4];
            #pragma unroll
            for (int mi = 0; mi < 2; mi++) {
                int r = wm * 32 + mi * 16 + g;
                const __half* x0 = wt + r * 72 + kb;
                const __half* x1 = wt + (r + 8) * 72 + kb;
                A[mi][0] = *(const uint32_t*)(x0 + 2 * k4);
                A[mi][1] = *(const uint32_t*)(x1 + 2 * k4);
                A[mi][2] = *(const uint32_t*)(x0 + 2 * k4 + 8);
                A[mi][3] = *(const uint32_t*)(x1 + 2 * k4 + 8);
            }
            #pragma unroll
            for (int ni = 0; ni < 8; ni++) {
                int cc = wn * 64 + ni * 8 + g;
                const __half* bp = ms + cc * 72 + kb;
                uint32_t B0 = *(const uint32_t*)(bp + 2 * k4);
                uint32_t B1 = *(const uint32_t*)(bp + 2 * k4 + 8);
                mmah(acc[0 * 8 + ni], A[0][0], A[0][1], A[0][2], A[0][3], B0, B1);
                mmah(acc[1 * 8 + ni], A[1][0], A[1][1], A[1][2], A[1][3], B0, B1);
            }
        }
        __syncthreads();
    }

    #pragma unroll
    for (int mi = 0; mi < 2; mi++) {
        #pragma unroll
        for (int ni = 0; ni < 8; ni++) {
            int cl = wn * 64 + ni * 8 + k4 * 2;
            float b0 = bout[col0 + cl], b1 = bout[col0 + cl + 1];
            int r0 = wm * 32 + mi * 16 + g;
            float* o0 = out + (size_t)(b * NN + n0 + r0) * DIMM + col0 + cl;
            float* o1 = out + (size_t)(b * NN + n0 + r0 + 8) * DIMM + col0 + cl;
            *(float2*)o0 = make_float2(acc[mi * 8 + ni][0] + b0, acc[mi * 8 + ni][1] + b1);
            *(float2*)o1 = make_float2(acc[mi * 8 + ni][2] + b0, acc[mi * 8 + ni][3] + b1);
        }
    }
}

// ---------------- launch ----------------
extern "C" void kernel_launch(void* const* d_in, const int* in_sizes, int n_in,
                              void* d_out, int out_size) {
    const float* x           = (const float*)d_in[0];
    const float* Wx          = (const float*)d_in[1];
    const float* bx          = (const float*)d_in[2];
    const float* Wfx         = (const float*)d_in[3];
    const float* bfx         = (const float*)d_in[4];
    const float* Wslice      = (const float*)d_in[5];
    const float* bslice      = (const float*)d_in[6];
    const float* temperature = (const float*)d_in[7];
    const float* Wq          = (const float*)d_in[8];
    const float* Wk          = (const float*)d_in[9];
    const float* Wv          = (const float*)d_in[10];
    const float* attn_scale  = (const float*)d_in[11];
    const float* srs         = (const float*)d_in[12];
    const float* Wout        = (const float*)d_in[13];
    const float* bout        = (const float*)d_in[14];
    float* out = (float*)d_out;

    const int K1S = 3 * 36864;                  // 110592
    const int K2S = 39040 * (int)sizeof(float); // 156160
    const int K3S = 3 * 36864;                  // 110592
    cudaFuncSetAttribute(k1, cudaFuncAttributeMaxDynamicSharedMemorySize, K1S);
    cudaFuncSetAttribute(k2, cudaFuncAttributeMaxDynamicSharedMemorySize, K2S);
    cudaFuncSetAttribute(k3, cudaFuncAttributeMaxDynamicSharedMemorySize, K3S);

    k_conv<<<8192, 256>>>(x);
    k_prep<<<dim3(HH, DIMM), 128>>>(Wx, bx, Wfx, bfx, Wslice, bslice, temperature);
    k1<<<dim3(HH, NN / 128, BB), 256, K1S>>>();
    k2<<<dim3(HH, BB), 256, K2S>>>(Wq, Wk, Wv, attn_scale, srs);
    k2m<<<dim3(HH, BB, 4), 256>>>(Wout);
    k3<<<dim3(2, NN / 128, BB), 256, K3S>>>(bout, out);
}

// round 13
// speedup vs baseline: 1.0335x; 1.0335x over previous
#include <cuda_runtime.h>
#include <cuda_fp16.h>
#include <math.h>
#include <stdint.h>

#define BB 4
#define NN 16384
#define DIMM 256
#define HH 8
#define DD 64
#define SS 64
#define INNERR 512

// ---------------- device scratch ----------------
__device__ __half g_xh[(size_t)BB * NN * DIMM];         // x in half
__device__ __half g_CWH[HH * 128 * DIMM];               // combined weight [h][col][k], half
__device__ float  g_Cb[HH * 128];                       // combined bias (fp32)
__device__ __half g_w[(size_t)BB * NN * INNERR];        // softmax slice weights [b][n][j], half
__device__ float  g_tok[BB * HH * SS * DD];             // accumulated tok (atomics)
__device__ float  g_norm[BB * HH * SS];                 // slice_norm (atomics)
__device__ float  g_ot[BB * HH * DD * SS];              // out_tok TRANSPOSED [b][h][d][s]
__device__ __half g_M[BB * DIMM * INNERR];              // M [b][o][j], half

// ---------------- helpers ----------------
__device__ __forceinline__ float tf32r(float f) {
    uint32_t u;
    asm("cvt.rna.tf32.f32 %0, %1;" : "=r"(u) : "f"(f));
    return __uint_as_float(u);
}
__device__ __forceinline__ uint32_t FB(float f) { return __float_as_uint(f); }
__device__ __forceinline__ uint32_t ph2(float a, float b) {
    __half2 h = __floats2half2_rn(a, b);
    return *(uint32_t*)&h;
}
__device__ __forceinline__ void cpa16(void* s, const void* g) {
    uint32_t sa = (uint32_t)__cvta_generic_to_shared(s);
    asm volatile("cp.async.cg.shared.global [%0], [%1], 16;\n" :: "r"(sa), "l"(g));
}
#define CPA_COMMIT asm volatile("cp.async.commit_group;\n" ::: "memory")
#define CPA_WAIT1  asm volatile("cp.async.wait_group 1;\n" ::: "memory")
#define CPA_WAIT0  asm volatile("cp.async.wait_group 0;\n" ::: "memory")

__device__ __forceinline__ void ldsm4(uint32_t* r, const __half* p) {
    uint32_t a = (uint32_t)__cvta_generic_to_shared(p);
    asm volatile("ldmatrix.sync.aligned.m8n8.x4.shared.b16 {%0,%1,%2,%3}, [%4];"
        : "=r"(r[0]), "=r"(r[1]), "=r"(r[2]), "=r"(r[3]) : "r"(a));
}

__device__ __forceinline__ void mmat(float* d, uint32_t a0, uint32_t a1, uint32_t a2, uint32_t a3,
                                     uint32_t b0, uint32_t b1) {
    asm volatile(
        "mma.sync.aligned.m16n8k8.row.col.f32.tf32.tf32.f32 "
        "{%0,%1,%2,%3},{%4,%5,%6,%7},{%8,%9},{%0,%1,%2,%3};"
        : "+f"(d[0]), "+f"(d[1]), "+f"(d[2]), "+f"(d[3])
        : "r"(a0), "r"(a1), "r"(a2), "r"(a3), "r"(b0), "r"(b1));
}

__device__ __forceinline__ void mmah(float* d, uint32_t a0, uint32_t a1, uint32_t a2, uint32_t a3,
                                     uint32_t b0, uint32_t b1) {
    asm volatile(
        "mma.sync.aligned.m16n8k16.row.col.f32.f16.f16.f32 "
        "{%0,%1,%2,%3},{%4,%5,%6,%7},{%8,%9},{%0,%1,%2,%3};"
        : "+f"(d[0]), "+f"(d[1]), "+f"(d[2]), "+f"(d[3])
        : "r"(a0), "r"(a1), "r"(a2), "r"(a3), "r"(b0), "r"(b1));
}

// ---------------- x -> half ----------------
__global__ void k_conv(const float* __restrict__ x) {
    size_t i = ((size_t)blockIdx.x * 256 + threadIdx.x) * 8;
    float4 a = *(const float4*)(x + i);
    float4 b = *(const float4*)(x + i + 4);
    uint4 p;
    p.x = ph2(a.x, a.y); p.y = ph2(a.z, a.w);
    p.z = ph2(b.x, b.y); p.w = ph2(b.z, b.w);
    *(uint4*)(g_xh + i) = p;
}

// ---------------- prep ----------------
__global__ void k_prep(const float* __restrict__ Wx, const float* __restrict__ bx,
                       const float* __restrict__ Wfx, const float* __restrict__ bfx,
                       const float* __restrict__ Wslice, const float* __restrict__ bslice,
                       const float* __restrict__ temperature) {
    int h = blockIdx.x;
    int k = blockIdx.y;
    int col = threadIdx.x;

    int gid = (h * 256 + k) * 128 + col;
    if (gid < BB * HH * SS * DD) g_tok[gid] = 0.f;
    if (gid < BB * HH * SS) g_norm[gid] = 0.f;

    float invt = 1.f / fmaxf(temperature[h], 1e-4f);
    float v;
    if (col < 64) {
        v = Wfx[(h * 64 + col) * DIMM + k];
    } else {
        int s = col - 64;
        float acc = 0.f;
        #pragma unroll 8
        for (int d = 0; d < 64; d++)
            acc += Wslice[s * 64 + d] * Wx[(h * 64 + d) * DIMM + k];
        v = acc * invt;
    }
    g_CWH[(h * 128 + col) * DIMM + k] = __float2half_rn(v);
    if (k == 0) {
        float bv;
        if (col < 64) {
            bv = bfx[h * 64 + col];
        } else {
            int s = col - 64;
            float acc = bslice[s];
            #pragma unroll 8
            for (int d = 0; d < 64; d++) acc += Wslice[s * 64 + d] * bx[h * 64 + d];
            bv = acc * invt;
        }
        g_Cb[h * 128 + col] = bv;
    }
}

// ---------------- pass 1: 2-stage pipelined fp16 mma (ldmatrix) + softmax + tok ----------------
// grid (H, N/128, B), block 256, dyn smem = 73728 B
__global__ __launch_bounds__(256, 2) void k1() {
    extern __shared__ float sm[];
    __half* base = (__half*)sm;
    const int h = blockIdx.x, nt = blockIdx.y, b = blockIdx.z;
    const int tid = threadIdx.x;
    const int lane = tid & 31, wid = tid >> 5;
    const int wm = wid & 3, wn = wid >> 2;
    const int g = lane >> 2, k4 = lane & 3;
    const int n0 = nt * 128;

    const __half* xh = g_xh + (size_t)(b * NN + n0) * DIMM;
    const __half* cw = g_CWH + h * 128 * DIMM;

    // ldmatrix per-lane offsets (in halves)
    uint32_t aoff[2], boff[4];
    #pragma unroll
    for (int mi = 0; mi < 2; mi++)
        aoff[mi] = (wm * 32 + mi * 16 + (lane & 15)) * 72 + ((lane >> 4) << 3);
    #pragma unroll
    for (int p = 0; p < 4; p++)
        boff[p] = (wn * 64 + p * 16 + ((lane >> 4) << 3) + (lane & 7)) * 72 + (((lane >> 3) & 1) << 3);

    float acc[16][4];
    #pragma unroll
    for (int i = 0; i < 16; i++)
        #pragma unroll
        for (int j = 0; j < 4; j++) acc[i][j] = 0.f;

    auto issue = [&](int c) {
        __half* xs = base + (c & 1) * 18432;
        __half* ws = xs + 9216;
        int kc = c * 64;
        for (int i = tid; i < 1024; i += 256) {
            int t = i >> 3, v8 = i & 7;
            cpa16(xs + t * 72 + v8 * 8, xh + (size_t)t * DIMM + kc + v8 * 8);
            cpa16(ws + t * 72 + v8 * 8, cw + (size_t)t * DIMM + kc + v8 * 8);
        }
        CPA_COMMIT;
    };

    issue(0);
    for (int c = 0; c < 4; c++) {
        if (c + 1 < 4) { issue(c + 1); CPA_WAIT1; } else { CPA_WAIT0; }
        __syncthreads();
        __half* xs = base + (c & 1) * 18432;
        __half* ws = xs + 9216;
        #pragma unroll
        for (int ks = 0; ks < 4; ks++) {
            const int kb = ks * 16;
            uint32_t A[2][4], Bf[4][4];
            ldsm4(A[0], xs + aoff[0] + kb);
            ldsm4(A[1], xs + aoff[1] + kb);
            #pragma unroll
            for (int p = 0; p < 4; p++) ldsm4(Bf[p], ws + boff[p] + kb);
            #pragma unroll
            for (int p = 0; p < 4; p++) {
                mmah(acc[0 * 8 + 2 * p],     A[0][0], A[0][1], A[0][2], A[0][3], Bf[p][0], Bf[p][1]);
                mmah(acc[1 * 8 + 2 * p],     A[1][0], A[1][1], A[1][2], A[1][3], Bf[p][0], Bf[p][1]);
                mmah(acc[0 * 8 + 2 * p + 1], A[0][0], A[0][1], A[0][2], A[0][3], Bf[p][2], Bf[p][3]);
                mmah(acc[1 * 8 + 2 * p + 1], A[1][0], A[1][1], A[1][2], A[1][3], Bf[p][2], Bf[p][3]);
            }
        }
        __syncthreads();
    }

    // epilogue: bias + stage fx (tf32-rounded fp32) and logits (fp32)
    float* fxs = sm;                 // [128][72]
    float* lgs = sm + 128 * 72;      // [128][72]
    {
        const float* cb = g_Cb + h * 128;
        float* dst = wn ? lgs : fxs;
        #pragma unroll
        for (int mi = 0; mi < 2; mi++) {
            int r0 = wm * 32 + mi * 16 + g;
            #pragma unroll
            for (int ni = 0; ni < 8; ni++) {
                int cl = ni * 8 + k4 * 2;
                float b0 = cb[wn * 64 + cl], b1 = cb[wn * 64 + cl + 1];
                float v00 = acc[mi * 8 + ni][0] + b0, v01 = acc[mi * 8 + ni][1] + b1;
                float v10 = acc[mi * 8 + ni][2] + b0, v11 = acc[mi * 8 + ni][3] + b1;
                if (!wn) { v00 = tf32r(v00); v01 = tf32r(v01); v10 = tf32r(v10); v11 = tf32r(v11); }
                dst[r0 * 72 + cl] = v00;
                dst[r0 * 72 + cl + 1] = v01;
                dst[(r0 + 8) * 72 + cl] = v10;
                dst[(r0 + 8) * 72 + cl + 1] = v11;
            }
        }
    }
    __syncthreads();

    // softmax: 128 tokens, 2 threads/token; write g_w as half
    {
        int tok = tid >> 1, q2 = tid & 1;
        float* row = lgs + tok * 72 + q2 * 32;
        float m = -1e30f;
        #pragma unroll
        for (int s = 0; s < 32; s++) m = fmaxf(m, row[s]);
        m = fmaxf(m, __shfl_xor_sync(0xffffffffu, m, 1));
        float e[32];
        float sum = 0.f;
        #pragma unroll
        for (int s = 0; s < 32; s++) { e[s] = __expf(row[s] - m); sum += e[s]; }
        sum += __shfl_xor_sync(0xffffffffu, sum, 1);
        float inv = 1.f / sum;
        float v[32];
        #pragma unroll
        for (int s = 0; s < 32; s++) { v[s] = e[s] * inv; row[s] = tf32r(v[s]); }
        __half* gw = g_w + (size_t)(b * NN + n0 + tok) * INNERR + h * 64 + q2 * 32;
        uint4* gp = (uint4*)gw;
        gp[0] = make_uint4(ph2(v[0], v[1]), ph2(v[2], v[3]), ph2(v[4], v[5]), ph2(v[6], v[7]));
        gp[1] = make_uint4(ph2(v[8], v[9]), ph2(v[10], v[11]), ph2(v[12], v[13]), ph2(v[14], v[15]));
        gp[2] = make_uint4(ph2(v[16], v[17]), ph2(v[18], v[19]), ph2(v[20], v[21]), ph2(v[22], v[23]));
        gp[3] = make_uint4(ph2(v[24], v[25]), ph2(v[26], v[27]), ph2(v[28], v[29]), ph2(v[30], v[31]));
    }
    __syncthreads();

    // slice_norm
    if (tid < 64) {
        float ns = 0.f;
        #pragma unroll 8
        for (int t = 0; t < 128; t++) ns += lgs[t * 72 + tid];
        atomicAdd(&g_norm[((size_t)b * HH + h) * 64 + tid], ns);
    }

    // tok[s][d] += sum_t w[t][s] * fx[t][d]  (tf32 mma)
    {
        float a2[4][4];
        #pragma unroll
        for (int i = 0; i < 4; i++)
            #pragma unroll
            for (int j = 0; j < 4; j++) a2[i][j] = 0.f;
        const int m0 = (wid & 3) * 16;
        const int dh = (wid >> 2) * 32;
        #pragma unroll
        for (int ks = 0; ks < 16; ks++) {
            const int kb = ks * 8;
            uint32_t A0 = FB(lgs[(kb + k4) * 72 + m0 + g]);
            uint32_t A1 = FB(lgs[(kb + k4) * 72 + m0 + g + 8]);
            uint32_t A2 = FB(lgs[(kb + k4 + 4) * 72 + m0 + g]);
            uint32_t A3 = FB(lgs[(kb + k4 + 4) * 72 + m0 + g + 8]);
            #pragma unroll
            for (int ni = 0; ni < 4; ni++) {
                int c = dh + ni * 8 + g;
                uint32_t B0 = FB(fxs[(kb + k4) * 72 + c]);
                uint32_t B1 = FB(fxs[(kb + k4 + 4) * 72 + c]);
                mmat(a2[ni], A0, A1, A2, A3, B0, B1);
            }
        }
        float* gt = g_tok + (size_t)((b * HH + h) * 64) * 64;
        #pragma unroll
        for (int ni = 0; ni < 4; ni++) {
            int s0 = m0 + g, c0 = dh + ni * 8 + k4 * 2;
            atomicAdd(gt + s0 * 64 + c0,           a2[ni][0]);
            atomicAdd(gt + s0 * 64 + c0 + 1,       a2[ni][1]);
            atomicAdd(gt + (s0 + 8) * 64 + c0,     a2[ni][2]);
            atomicAdd(gt + (s0 + 8) * 64 + c0 + 1, a2[ni][3]);
        }
    }
}

// ---------------- k2: cross-slice attention only (writes g_ot transposed) ----------------
__device__ __forceinline__ void gemm16(const float* __restrict__ A, int sa,
                                       const float* __restrict__ B /* stride 68 */,
                                       int tr, int tc, float o[4][4]) {
    #pragma unroll
    for (int i = 0; i < 4; i++)
        #pragma unroll
        for (int j = 0; j < 4; j++) o[i][j] = 0.f;
    #pragma unroll 4
    for (int e = 0; e < 64; e++) {
        float4 bv = *(const float4*)(B + e * 68 + tc * 4);
        #pragma unroll
        for (int i = 0; i < 4; i++) {
            float a = A[(tr * 4 + i) * sa + e];
            o[i][0] += a * bv.x; o[i][1] += a * bv.y;
            o[i][2] += a * bv.z; o[i][3] += a * bv.w;
        }
    }
}

// grid (H, B), block 256, dyn smem = 156160 B
__global__ void k2(const float* __restrict__ Wq, const float* __restrict__ Wk,
                   const float* __restrict__ Wv, const float* __restrict__ ascale_p,
                   const float* __restrict__ srs_p) {
    extern __shared__ float sm[];
    float* rn   = sm;                    // [512]
    float* tokn = sm + 512;              // [64][65]
    float* kv   = sm + 4672;             // [64][65]
    float* wq   = sm + 8832;             // [64][68] transposed [e][d]
    float* wk   = sm + 13184;            // [64][68]
    float* wv   = sm + 17536;            // [64][68]
    float* qq   = sm + 21888;            // [64][65]
    float* kkt  = sm + 26048;            // [64][68]
    float* vv   = sm + 30400;            // [64][68]
    float* att  = sm + 34752;            // [64][65]
    float* nqi  = sm + 38912;            // [64]
    float* nki  = sm + 38976;            // [64]
    const int h = blockIdx.x, b = blockIdx.y;
    const int tid = threadIdx.x;
    const int tr = tid >> 4, tc = tid & 15;

    for (int i = tid; i < 512; i += 256) rn[i] = __frcp_rn(g_norm[b * 512 + i] + 1e-5f);
    for (int i = tid; i < 4096; i += 256) {
        int e = i & 63, d = i >> 6;
        wq[e * 68 + d] = Wq[d * 64 + e];
        wk[e * 68 + d] = Wk[d * 64 + e];
        wv[e * 68 + d] = Wv[d * 64 + e];
    }
    __syncthreads();

    for (int i = tid; i < 4096; i += 256) {
        int s = i >> 6, d = i & 63;
        float accv = 0.f;
        #pragma unroll
        for (int hh = 0; hh < 8; hh++)
            accv += g_tok[((b * 8 + hh) * 64 + s) * 64 + d] * rn[hh * 64 + s];
        kv[s * 65 + d] = accv * 0.125f;
        tokn[s * 65 + d] = g_tok[((b * 8 + h) * 64 + s) * 64 + d] * rn[h * 64 + s];
    }
    __syncthreads();

    // merged q/k/v GEMMs
    {
        float oq[4][4], ok[4][4], ov[4][4];
        #pragma unroll
        for (int i = 0; i < 4; i++)
            #pragma unroll
            for (int j = 0; j < 4; j++) { oq[i][j] = 0.f; ok[i][j] = 0.f; ov[i][j] = 0.f; }
        #pragma unroll 2
        for (int e = 0; e < 64; e++) {
            float4 bq = *(const float4*)(wq + e * 68 + tc * 4);
            float4 bk = *(const float4*)(wk + e * 68 + tc * 4);
            float4 bv = *(const float4*)(wv + e * 68 + tc * 4);
            #pragma unroll
            for (int i = 0; i < 4; i++) {
                float aq = tokn[(tr * 4 + i) * 65 + e];
                float ak = kv[(tr * 4 + i) * 65 + e];
                oq[i][0] += aq * bq.x; oq[i][1] += aq * bq.y; oq[i][2] += aq * bq.z; oq[i][3] += aq * bq.w;
                ok[i][0] += ak * bk.x; ok[i][1] += ak * bk.y; ok[i][2] += ak * bk.z; ok[i][3] += ak * bk.w;
                ov[i][0] += ak * bv.x; ov[i][1] += ak * bv.y; ov[i][2] += ak * bv.z; ov[i][3] += ak * bv.w;
            }
        }
        #pragma unroll
        for (int i = 0; i < 4; i++)
            #pragma unroll
            for (int j = 0; j < 4; j++) {
                qq[(tr * 4 + i) * 65 + tc * 4 + j]  = oq[i][j];
                kkt[(tc * 4 + j) * 68 + tr * 4 + i] = ok[i][j];
                vv[(tr * 4 + i) * 68 + tc * 4 + j]  = ov[i][j];
            }
    }
    __syncthreads();

    if (tid < 64) {
        float s2 = 0.f;
        #pragma unroll 8
        for (int d = 0; d < 64; d++) { float v = qq[tid * 65 + d]; s2 += v * v; }
        nqi[tid] = rsqrtf(fmaxf(s2, 1e-24f));
    } else if (tid < 128) {
        int s = tid - 64;
        float s2 = 0.f;
        #pragma unroll 8
        for (int d = 0; d < 64; d++) { float v = kkt[d * 68 + s]; s2 += v * v; }
        nki[s] = rsqrtf(fmaxf(s2, 1e-24f));
    }
    __syncthreads();

    float o[4][4];
    gemm16(qq, 65, kkt, tr, tc, o);
    {
        float asc = ascale_p[h];
        float rq[4], rk[4];
        #pragma unroll
        for (int i = 0; i < 4; i++) rq[i] = asc * nqi[tr * 4 + i];
        #pragma unroll
        for (int j = 0; j < 4; j++) rk[j] = nki[tc * 4 + j];
        #pragma unroll
        for (int i = 0; i < 4; i++)
            #pragma unroll
            for (int j = 0; j < 4; j++)
                att[(tr * 4 + i) * 65 + tc * 4 + j] = o[i][j] * rq[i] * rk[j];
    }
    __syncthreads();

    // softmax rows of att
    {
        int gg = tid >> 2, q4 = tid & 3;
        float* row = att + gg * 65;
        float m = -1e30f;
        #pragma unroll
        for (int s = 0; s < 16; s++) m = fmaxf(m, row[q4 * 16 + s]);
        m = fmaxf(m, __shfl_xor_sync(0xffffffffu, m, 1));
        m = fmaxf(m, __shfl_xor_sync(0xffffffffu, m, 2));
        float e[16];
        float sum = 0.f;
        #pragma unroll
        for (int s = 0; s < 16; s++) { e[s] = __expf(row[q4 * 16 + s] - m); sum += e[s]; }
        sum += __shfl_xor_sync(0xffffffffu, sum, 1);
        sum += __shfl_xor_sync(0xffffffffu, sum, 2);
        float inv = 1.f / sum;
        #pragma unroll
        for (int s = 0; s < 16; s++) row[q4 * 16 + s] = e[s] * inv;
    }
    __syncthreads();

    // out_tok = att @ v + sr * tokn -> write g_ot transposed [b][h][d][s]
    gemm16(att, 65, vv, tr, tc, o);
    {
        float sr = srs_p[0];
        float* gb = g_ot + (size_t)((b * 8 + h) * 64) * 64;
        #pragma unroll
        for (int j = 0; j < 4; j++) {
            int d = tc * 4 + j;
            float4 v4;
            v4.x = o[0][j] + sr * tokn[(tr * 4 + 0) * 65 + d];
            v4.y = o[1][j] + sr * tokn[(tr * 4 + 1) * 65 + d];
            v4.z = o[2][j] + sr * tokn[(tr * 4 + 2) * 65 + d];
            v4.w = o[3][j] + sr * tokn[(tr * 4 + 3) * 65 + d];
            *(float4*)(gb + d * 64 + tr * 4) = v4;
        }
    }
}

// ---------------- k2m: M[b][o][h*64+s] = sum_d Wout[o][h*64+d] * ot[b][h][d][s] ----------------
// grid (H, B, 4), block 256
__global__ void k2m(const float* __restrict__ Wout) {
    __shared__ float wos[64 * 68];
    __shared__ float ots[64 * 68];
    const int h = blockIdx.x, b = blockIdx.y, og = blockIdx.z;
    const int o0 = og * 64;
    const int tid = threadIdx.x;

    for (int i = tid; i < 4096; i += 256) {
        int oo = i >> 6, d = i & 63;
        wos[oo * 68 + d] = Wout[(size_t)(o0 + oo) * INNERR + h * 64 + d];
    }
    const float* gb = g_ot + (size_t)((b * 8 + h) * 64) * 64;
    for (int i = tid; i < 4096; i += 256) {
        int d = i >> 6, s = i & 63;
        ots[d * 68 + s] = gb[d * 64 + s];
    }
    __syncthreads();

    const int to = tid >> 2;        // o in [0,64)
    const int ts = tid & 3;         // s block of 16
    float accm[16];
    #pragma unroll
    for (int j = 0; j < 16; j++) accm[j] = 0.f;
    #pragma unroll 4
    for (int d = 0; d < 64; d++) {
        float a = wos[to * 68 + d];
        float4 s0 = *(const float4*)(ots + d * 68 + ts * 16);
        float4 s1 = *(const float4*)(ots + d * 68 + ts * 16 + 4);
        float4 s2 = *(const float4*)(ots + d * 68 + ts * 16 + 8);
        float4 s3 = *(const float4*)(ots + d * 68 + ts * 16 + 12);
        accm[0]  += a * s0.x; accm[1]  += a * s0.y; accm[2]  += a * s0.z; accm[3]  += a * s0.w;
        accm[4]  += a * s1.x; accm[5]  += a * s1.y; accm[6]  += a * s1.z; accm[7]  += a * s1.w;
        accm[8]  += a * s2.x; accm[9]  += a * s2.y; accm[10] += a * s2.z; accm[11] += a * s2.w;
        accm[12] += a * s3.x; accm[13] += a * s3.y; accm[14] += a * s3.z; accm[15] += a * s3.w;
    }
    __half* mp = g_M + ((size_t)(b * DIMM + o0 + to)) * INNERR + h * 64 + ts * 16;
    uint4 p0, p1;
    p0.x = ph2(accm[0], accm[1]);   p0.y = ph2(accm[2], accm[3]);
    p0.z = ph2(accm[4], accm[5]);   p0.w = ph2(accm[6], accm[7]);
    p1.x = ph2(accm[8], accm[9]);   p1.y = ph2(accm[10], accm[11]);
    p1.z = ph2(accm[12], accm[13]); p1.w = ph2(accm[14], accm[15]);
    ((uint4*)mp)[0] = p0;
    ((uint4*)mp)[1] = p1;
}

// ---------------- pass 2: 2-stage pipelined y = w @ M^T + bout (ldmatrix) ----------------
// grid (2, N/128, B), block 256, dyn smem = 73728 B
__global__ __launch_bounds__(256, 2) void k3(const float* __restrict__ bout, float* __restrict__ out) {
    extern __shared__ float sm[];
    __half* base = (__half*)sm;
    const int cb = blockIdx.x, nt = blockIdx.y, b = blockIdx.z;
    const int tid = threadIdx.x;
    const int lane = tid & 31, wid = tid >> 5;
    const int wm = wid & 3, wn = wid >> 2;
    const int g = lane >> 2, k4 = lane & 3;
    const int n0 = nt * 128, col0 = cb * 128;
    const __half* wp = g_w + (size_t)(b * NN + n0) * INNERR;
    const __half* mp = g_M + (size_t)b * DIMM * INNERR + (size_t)col0 * INNERR;

    uint32_t aoff[2], boff[4];
    #pragma unroll
    for (int mi = 0; mi < 2; mi++)
        aoff[mi] = (wm * 32 + mi * 16 + (lane & 15)) * 72 + ((lane >> 4) << 3);
    #pragma unroll
    for (int p = 0; p < 4; p++)
        boff[p] = (wn * 64 + p * 16 + ((lane >> 4) << 3) + (lane & 7)) * 72 + (((lane >> 3) & 1) << 3);

    float acc[16][4];
    #pragma unroll
    for (int i = 0; i < 16; i++)
        #pragma unroll
        for (int j = 0; j < 4; j++) acc[i][j] = 0.f;

    auto issue = [&](int c) {
        __half* wt = base + (c & 1) * 18432;
        __half* ms = wt + 9216;
        int kc = c * 64;
        for (int i = tid; i < 1024; i += 256) {
            int t = i >> 3, v8 = i & 7;
            cpa16(wt + t * 72 + v8 * 8, wp + (size_t)t * INNERR + kc + v8 * 8);
            cpa16(ms + t * 72 + v8 * 8, mp + (size_t)t * INNERR + kc + v8 * 8);
        }
        CPA_COMMIT;
    };

    issue(0);
    for (int c = 0; c < 8; c++) {
        if (c + 1 < 8) { issue(c + 1); CPA_WAIT1; } else { CPA_WAIT0; }
        __syncthreads();
        __half* wt = base + (c & 1) * 18432;
        __half* ms = wt + 9216;
        #pragma unroll
        for (int ks = 0; ks < 4; ks++) {
            const int kb = ks * 16;
            uint32_t A[2][4], Bf[4][4];
            ldsm4(A[0], wt + aoff[0] + kb);
            ldsm4(A[1], wt + aoff[1] + kb);
            #pragma unroll
            for (int p = 0; p < 4; p++) ldsm4(Bf[p], ms + boff[p] + kb);
            #pragma unroll
            for (int p = 0; p < 4; p++) {
                mmah(acc[0 * 8 + 2 * p],     A[0][0], A[0][1], A[0][2], A[0][3], Bf[p][0], Bf[p][1]);
                mmah(acc[1 * 8 + 2 * p],     A[1][0], A[1][1], A[1][2], A[1][3], Bf[p][0], Bf[p][1]);
                mmah(acc[0 * 8 + 2 * p + 1], A[0][0], A[0][1], A[0][2], A[0][3], Bf[p][2], Bf[p][3]);
                mmah(acc[1 * 8 + 2 * p + 1], A[1][0], A[1][1], A[1][2], A[1][3], Bf[p][2], Bf[p][3]);
            }
        }
        __syncthreads();
    }

    #pragma unroll
    for (int mi = 0; mi < 2; mi++) {
        #pragma unroll
        for (int ni = 0; ni < 8; ni++) {
            int cl = wn * 64 + ni * 8 + k4 * 2;
            float b0 = bout[col0 + cl], b1 = bout[col0 + cl + 1];
            int r0 = wm * 32 + mi * 16 + g;
            float* o0 = out + (size_t)(b * NN + n0 + r0) * DIMM + col0 + cl;
            float* o1 = out + (size_t)(b * NN + n0 + r0 + 8) * DIMM + col0 + cl;
            *(float2*)o0 = make_float2(acc[mi * 8 + ni][0] + b0, acc[mi * 8 + ni][1] + b1);
            *(float2*)o1 = make_float2(acc[mi * 8 + ni][2] + b0, acc[mi * 8 + ni][3] + b1);
        }
    }
}

// ---------------- launch ----------------
extern "C" void kernel_launch(void* const* d_in, const int* in_sizes, int n_in,
                              void* d_out, int out_size) {
    const float* x           = (const float*)d_in[0];
    const float* Wx          = (const float*)d_in[1];
    const float* bx          = (const float*)d_in[2];
    const float* Wfx         = (const float*)d_in[3];
    const float* bfx         = (const float*)d_in[4];
    const float* Wslice      = (const float*)d_in[5];
    const float* bslice      = (const float*)d_in[6];
    const float* temperature = (const float*)d_in[7];
    const float* Wq          = (const float*)d_in[8];
    const float* Wk          = (const float*)d_in[9];
    const float* Wv          = (const float*)d_in[10];
    const float* attn_scale  = (const float*)d_in[11];
    const float* srs         = (const float*)d_in[12];
    const float* Wout        = (const float*)d_in[13];
    const float* bout        = (const float*)d_in[14];
    float* out = (float*)d_out;

    const int K1S = 2 * 36864;                  // 73728
    const int K2S = 39040 * (int)sizeof(float); // 156160
    const int K3S = 2 * 36864;                  // 73728
    cudaFuncSetAttribute(k1, cudaFuncAttributeMaxDynamicSharedMemorySize, K1S);
    cudaFuncSetAttribute(k2, cudaFuncAttributeMaxDynamicSharedMemorySize, K2S);
    cudaFuncSetAttribute(k3, cudaFuncAttributeMaxDynamicSharedMemorySize, K3S);

    k_conv<<<8192, 256>>>(x);
    k_prep<<<dim3(HH, DIMM), 128>>>(Wx, bx, Wfx, bfx, Wslice, bslice, temperature);
    k1<<<dim3(HH, NN / 128, BB), 256, K1S>>>();
    k2<<<dim3(HH, BB), 256, K2S>>>(Wq, Wk, Wv, attn_scale, srs);
    k2m<<<dim3(HH, BB, 4), 256>>>(Wout);
    k3<<<dim3(2, NN / 128, BB), 256, K3S>>>(bout, out);
}

// round 14
// speedup vs baseline: 1.0578x; 1.0235x over previous
#include <cuda_runtime.h>
#include <cuda_fp16.h>
#include <math.h>
#include <stdint.h>

#define BB 4
#define NN 16384
#define DIMM 256
#define HH 8
#define DD 64
#define SS 64
#define INNERR 512

// ---------------- device scratch ----------------
__device__ __half g_xh[(size_t)BB * NN * DIMM];         // x in half
__device__ __half g_CWH[HH * 128 * DIMM];               // combined weight [h][col][k], half (logit cols pre-scaled by log2e)
__device__ float  g_Cb[HH * 128];                       // combined bias (fp32, logit part pre-scaled by log2e)
__device__ __half g_w[(size_t)BB * NN * INNERR];        // softmax slice weights [b][n][j], half
__device__ float  g_tok[BB * HH * SS * DD];             // accumulated tok (atomics)
__device__ float  g_norm[BB * HH * SS];                 // slice_norm (atomics)
__device__ float  g_ot[BB * HH * DD * SS];              // out_tok TRANSPOSED [b][h][d][s]
__device__ __half g_M[BB * DIMM * INNERR];              // M [b][o][j], half

// ---------------- helpers ----------------
__device__ __forceinline__ uint32_t FB(float f) { return __float_as_uint(f); }
__device__ __forceinline__ uint32_t ph2(float a, float b) {
    __half2 h = __floats2half2_rn(a, b);
    return *(uint32_t*)&h;
}
__device__ __forceinline__ void cpa16(void* s, const void* g) {
    uint32_t sa = (uint32_t)__cvta_generic_to_shared(s);
    asm volatile("cp.async.cg.shared.global [%0], [%1], 16;\n" :: "r"(sa), "l"(g));
}
#define CPA_COMMIT asm volatile("cp.async.commit_group;\n" ::: "memory")
#define CPA_WAIT1  asm volatile("cp.async.wait_group 1;\n" ::: "memory")
#define CPA_WAIT0  asm volatile("cp.async.wait_group 0;\n" ::: "memory")

__device__ __forceinline__ void ldsm4(uint32_t* r, const __half* p) {
    uint32_t a = (uint32_t)__cvta_generic_to_shared(p);
    asm volatile("ldmatrix.sync.aligned.m8n8.x4.shared.b16 {%0,%1,%2,%3}, [%4];"
        : "=r"(r[0]), "=r"(r[1]), "=r"(r[2]), "=r"(r[3]) : "r"(a));
}

__device__ __forceinline__ void mmat(float* d, uint32_t a0, uint32_t a1, uint32_t a2, uint32_t a3,
                                     uint32_t b0, uint32_t b1) {
    asm volatile(
        "mma.sync.aligned.m16n8k8.row.col.f32.tf32.tf32.f32 "
        "{%0,%1,%2,%3},{%4,%5,%6,%7},{%8,%9},{%0,%1,%2,%3};"
        : "+f"(d[0]), "+f"(d[1]), "+f"(d[2]), "+f"(d[3])
        : "r"(a0), "r"(a1), "r"(a2), "r"(a3), "r"(b0), "r"(b1));
}

__device__ __forceinline__ void mmah(float* d, uint32_t a0, uint32_t a1, uint32_t a2, uint32_t a3,
                                     uint32_t b0, uint32_t b1) {
    asm volatile(
        "mma.sync.aligned.m16n8k16.row.col.f32.f16.f16.f32 "
        "{%0,%1,%2,%3},{%4,%5,%6,%7},{%8,%9},{%0,%1,%2,%3};"
        : "+f"(d[0]), "+f"(d[1]), "+f"(d[2]), "+f"(d[3])
        : "r"(a0), "r"(a1), "r"(a2), "r"(a3), "r"(b0), "r"(b1));
}

// fast scalar 2^x (MUFU)
__device__ __forceinline__ float ex2f(float x) {
    float r; asm("ex2.approx.ftz.f32 %0, %1;" : "=f"(r) : "f"(x)); return r;
}
// packed f32x2 ops
__device__ __forceinline__ unsigned long long pka(unsigned long long a, unsigned long long b) {
    unsigned long long r; asm("add.rn.f32x2 %0, %1, %2;" : "=l"(r) : "l"(a), "l"(b)); return r;
}
__device__ __forceinline__ unsigned long long pkm(unsigned long long a, unsigned long long b) {
    unsigned long long r; asm("mul.rn.f32x2 %0, %1, %2;" : "=l"(r) : "l"(a), "l"(b)); return r;
}
__device__ __forceinline__ unsigned long long pkf(unsigned long long a, unsigned long long b, unsigned long long c) {
    unsigned long long r; asm("fma.rn.f32x2 %0, %1, %2, %3;" : "=l"(r) : "l"(a), "l"(b), "l"(c)); return r;
}
__device__ __forceinline__ unsigned long long mk2(float x, float y) {
    unsigned long long r; asm("mov.b64 %0, {%1,%2};" : "=l"(r) : "f"(x), "f"(y)); return r;
}
__device__ __forceinline__ void un2(unsigned long long v, float& x, float& y) {
    asm("mov.b64 {%0,%1}, %2;" : "=f"(x), "=f"(y) : "l"(v));
}
__device__ __forceinline__ unsigned long long dup2(float v) {
    uint32_t b = __float_as_uint(v);
    return ((unsigned long long)b << 32) | b;
}

// ---------------- x -> half ----------------
__global__ void k_conv(const float* __restrict__ x) {
    size_t i = ((size_t)blockIdx.x * 256 + threadIdx.x) * 8;
    float4 a = *(const float4*)(x + i);
    float4 b = *(const float4*)(x + i + 4);
    uint4 p;
    p.x = ph2(a.x, a.y); p.y = ph2(a.z, a.w);
    p.z = ph2(b.x, b.y); p.w = ph2(b.z, b.w);
    *(uint4*)(g_xh + i) = p;
}

// ---------------- prep (logit columns pre-scaled by log2(e)) ----------------
__global__ void k_prep(const float* __restrict__ Wx, const float* __restrict__ bx,
                       const float* __restrict__ Wfx, const float* __restrict__ bfx,
                       const float* __restrict__ Wslice, const float* __restrict__ bslice,
                       const float* __restrict__ temperature) {
    const float LOG2E = 1.4426950408889634f;
    int h = blockIdx.x;
    int k = blockIdx.y;
    int col = threadIdx.x;

    int gid = (h * 256 + k) * 128 + col;
    if (gid < BB * HH * SS * DD) g_tok[gid] = 0.f;
    if (gid < BB * HH * SS) g_norm[gid] = 0.f;

    float invt = LOG2E / fmaxf(temperature[h], 1e-4f);
    float v;
    if (col < 64) {
        v = Wfx[(h * 64 + col) * DIMM + k];
    } else {
        int s = col - 64;
        float acc = 0.f;
        #pragma unroll 8
        for (int d = 0; d < 64; d++)
            acc += Wslice[s * 64 + d] * Wx[(h * 64 + d) * DIMM + k];
        v = acc * invt;
    }
    g_CWH[(h * 128 + col) * DIMM + k] = __float2half_rn(v);
    if (k == 0) {
        float bv;
        if (col < 64) {
            bv = bfx[h * 64 + col];
        } else {
            int s = col - 64;
            float acc = bslice[s];
            #pragma unroll 8
            for (int d = 0; d < 64; d++) acc += Wslice[s * 64 + d] * bx[h * 64 + d];
            bv = acc * invt;
        }
        g_Cb[h * 128 + col] = bv;
    }
}

// ---------------- pass 1: fp16 mma (ldmatrix, 2-stage) + dual-pipe softmax + tok ----------------
// grid (H, N/128, B), block 256, dyn smem = 73728 B
__global__ __launch_bounds__(256, 2) void k1() {
    extern __shared__ float sm[];
    __half* base = (__half*)sm;
    const int h = blockIdx.x, nt = blockIdx.y, b = blockIdx.z;
    const int tid = threadIdx.x;
    const int lane = tid & 31, wid = tid >> 5;
    const int wm = wid & 3, wn = wid >> 2;
    const int g = lane >> 2, k4 = lane & 3;
    const int n0 = nt * 128;

    const __half* xh = g_xh + (size_t)(b * NN + n0) * DIMM;
    const __half* cw = g_CWH + h * 128 * DIMM;

    uint32_t aoff[2], boff[4];
    #pragma unroll
    for (int mi = 0; mi < 2; mi++)
        aoff[mi] = (wm * 32 + mi * 16 + (lane & 15)) * 72 + ((lane >> 4) << 3);
    #pragma unroll
    for (int p = 0; p < 4; p++)
        boff[p] = (wn * 64 + p * 16 + ((lane >> 4) << 3) + (lane & 7)) * 72 + (((lane >> 3) & 1) << 3);

    float acc[16][4];
    #pragma unroll
    for (int i = 0; i < 16; i++)
        #pragma unroll
        for (int j = 0; j < 4; j++) acc[i][j] = 0.f;

    auto issue = [&](int c) {
        __half* xs = base + (c & 1) * 18432;
        __half* ws = xs + 9216;
        int kc = c * 64;
        for (int i = tid; i < 1024; i += 256) {
            int t = i >> 3, v8 = i & 7;
            cpa16(xs + t * 72 + v8 * 8, xh + (size_t)t * DIMM + kc + v8 * 8);
            cpa16(ws + t * 72 + v8 * 8, cw + (size_t)t * DIMM + kc + v8 * 8);
        }
        CPA_COMMIT;
    };

    issue(0);
    for (int c = 0; c < 4; c++) {
        if (c + 1 < 4) { issue(c + 1); CPA_WAIT1; } else { CPA_WAIT0; }
        __syncthreads();
        __half* xs = base + (c & 1) * 18432;
        __half* ws = xs + 9216;
        #pragma unroll
        for (int ks = 0; ks < 4; ks++) {
            const int kb = ks * 16;
            uint32_t A[2][4], Bf[4][4];
            ldsm4(A[0], xs + aoff[0] + kb);
            ldsm4(A[1], xs + aoff[1] + kb);
            #pragma unroll
            for (int p = 0; p < 4; p++) ldsm4(Bf[p], ws + boff[p] + kb);
            #pragma unroll
            for (int p = 0; p < 4; p++) {
                mmah(acc[0 * 8 + 2 * p],     A[0][0], A[0][1], A[0][2], A[0][3], Bf[p][0], Bf[p][1]);
                mmah(acc[1 * 8 + 2 * p],     A[1][0], A[1][1], A[1][2], A[1][3], Bf[p][0], Bf[p][1]);
                mmah(acc[0 * 8 + 2 * p + 1], A[0][0], A[0][1], A[0][2], A[0][3], Bf[p][2], Bf[p][3]);
                mmah(acc[1 * 8 + 2 * p + 1], A[1][0], A[1][1], A[1][2], A[1][3], Bf[p][2], Bf[p][3]);
            }
        }
        __syncthreads();
    }

    // epilogue: bias + stage fx and logits (raw fp32; mma.tf32 truncates in HW)
    float* fxs = sm;                 // [128][72]
    float* lgs = sm + 128 * 72;      // [128][72]
    {
        const float* cb = g_Cb + h * 128;
        float* dst = wn ? lgs : fxs;
        #pragma unroll
        for (int mi = 0; mi < 2; mi++) {
            int r0 = wm * 32 + mi * 16 + g;
            #pragma unroll
            for (int ni = 0; ni < 8; ni++) {
                int cl = ni * 8 + k4 * 2;
                float b0 = cb[wn * 64 + cl], b1 = cb[wn * 64 + cl + 1];
                dst[r0 * 72 + cl]           = acc[mi * 8 + ni][0] + b0;
                dst[r0 * 72 + cl + 1]       = acc[mi * 8 + ni][1] + b1;
                dst[(r0 + 8) * 72 + cl]     = acc[mi * 8 + ni][2] + b0;
                dst[(r0 + 8) * 72 + cl + 1] = acc[mi * 8 + ni][3] + b1;
            }
        }
    }
    __syncthreads();

    // softmax (logits pre-scaled by log2e, so w = 2^t / sum(2^t); no max-sub needed):
    // 128 tokens, 2 threads/token (32 values each); 20 values via MUFU, 12 via packed f32x2 poly.
    {
        int tok = tid >> 1, q2 = tid & 1;
        float* row = lgs + tok * 72 + q2 * 32;
        float t[32];
        #pragma unroll
        for (int s4 = 0; s4 < 8; s4++) *(float4*)(t + 4 * s4) = *(float4*)(row + 4 * s4);

        const unsigned long long MAG  = dup2(12582912.0f);
        const unsigned long long NMAG = dup2(-12582912.0f);
        const unsigned long long NONE = dup2(-1.0f);
        const unsigned long long C4 = dup2(0.00961813f);
        const unsigned long long C3 = dup2(0.05550411f);
        const unsigned long long C2 = dup2(0.24022651f);
        const unsigned long long C1 = dup2(0.69314718f);
        const unsigned long long C0 = dup2(1.0f);

        unsigned long long ep[16];
        #pragma unroll
        for (int i = 0; i < 16; i++) {
            float tx = t[2 * i], ty = t[2 * i + 1];
            if (i < 10) {
                ep[i] = mk2(ex2f(tx), ex2f(ty));
            } else {
                unsigned long long t2 = mk2(tx, ty);
                unsigned long long z  = pka(t2, MAG);       // round-to-int in low bits
                unsigned long long nf = pka(z, NMAG);       // n (float)
                unsigned long long f  = pkf(nf, NONE, t2);  // f = t - n in [-0.5, 0.5]
                unsigned long long p  = pkf(f, C4, C3);
                p = pkf(p, f, C2);
                p = pkf(p, f, C1);
                p = pkf(p, f, C0);
                float zx, zy, px, py;
                un2(z, zx, zy);
                un2(p, px, py);
                float rx = __uint_as_float(__float_as_uint(px) + (__float_as_uint(zx) << 23));
                float ry = __uint_as_float(__float_as_uint(py) + (__float_as_uint(zy) << 23));
                ep[i] = mk2(rx, ry);
            }
        }
        // packed sum
        unsigned long long a2 = ep[0];
        #pragma unroll
        for (int i = 1; i < 16; i++) a2 = pka(a2, ep[i]);
        float ax, ay;
        un2(a2, ax, ay);
        float sum = ax + ay;
        sum += __shfl_xor_sync(0xffffffffu, sum, 1);
        float inv;
        asm("rcp.approx.ftz.f32 %0, %1;" : "=f"(inv) : "f"(sum));
        unsigned long long inv2 = mk2(inv, inv);

        uint32_t hw[16];
        #pragma unroll
        for (int i = 0; i < 8; i++) {
            unsigned long long w0 = pkm(ep[2 * i], inv2);
            unsigned long long w1 = pkm(ep[2 * i + 1], inv2);
            float a0, a1, b0, b1;
            un2(w0, a0, a1);
            un2(w1, b0, b1);
            *(float4*)(row + 4 * i) = make_float4(a0, a1, b0, b1);
            hw[2 * i]     = ph2(a0, a1);
            hw[2 * i + 1] = ph2(b0, b1);
        }
        __half* gw = g_w + (size_t)(b * NN + n0 + tok) * INNERR + h * 64 + q2 * 32;
        uint4* gp = (uint4*)gw;
        gp[0] = make_uint4(hw[0], hw[1], hw[2], hw[3]);
        gp[1] = make_uint4(hw[4], hw[5], hw[6], hw[7]);
        gp[2] = make_uint4(hw[8], hw[9], hw[10], hw[11]);
        gp[3] = make_uint4(hw[12], hw[13], hw[14], hw[15]);
    }
    __syncthreads();

    // slice_norm
    if (tid < 64) {
        float ns = 0.f;
        #pragma unroll 8
        for (int t = 0; t < 128; t++) ns += lgs[t * 72 + tid];
        atomicAdd(&g_norm[((size_t)b * HH + h) * 64 + tid], ns);
    }

    // tok[s][d] += sum_t w[t][s] * fx[t][d]  (tf32 mma; HW truncation of f32 inputs)
    {
        float a2[4][4];
        #pragma unroll
        for (int i = 0; i < 4; i++)
            #pragma unroll
            for (int j = 0; j < 4; j++) a2[i][j] = 0.f;
        const int m0 = (wid & 3) * 16;
        const int dh = (wid >> 2) * 32;
        #pragma unroll
        for (int ks = 0; ks < 16; ks++) {
            const int kb = ks * 8;
            uint32_t A0 = FB(lgs[(kb + k4) * 72 + m0 + g]);
            uint32_t A1 = FB(lgs[(kb + k4) * 72 + m0 + g + 8]);
            uint32_t A2 = FB(lgs[(kb + k4 + 4) * 72 + m0 + g]);
            uint32_t A3 = FB(lgs[(kb + k4 + 4) * 72 + m0 + g + 8]);
            #pragma unroll
            for (int ni = 0; ni < 4; ni++) {
                int c = dh + ni * 8 + g;
                uint32_t B0 = FB(fxs[(kb + k4) * 72 + c]);
                uint32_t B1 = FB(fxs[(kb + k4 + 4) * 72 + c]);
                mmat(a2[ni], A0, A1, A2, A3, B0, B1);
            }
        }
        float* gt = g_tok + (size_t)((b * HH + h) * 64) * 64;
        #pragma unroll
        for (int ni = 0; ni < 4; ni++) {
            int s0 = m0 + g, c0 = dh + ni * 8 + k4 * 2;
            atomicAdd(gt + s0 * 64 + c0,           a2[ni][0]);
            atomicAdd(gt + s0 * 64 + c0 + 1,       a2[ni][1]);
            atomicAdd(gt + (s0 + 8) * 64 + c0,     a2[ni][2]);
            atomicAdd(gt + (s0 + 8) * 64 + c0 + 1, a2[ni][3]);
        }
    }
}

// ---------------- k2: cross-slice attention only (writes g_ot transposed) ----------------
__device__ __forceinline__ void gemm16(const float* __restrict__ A, int sa,
                                       const float* __restrict__ B /* stride 68 */,
                                       int tr, int tc, float o[4][4]) {
    #pragma unroll
    for (int i = 0; i < 4; i++)
        #pragma unroll
        for (int j = 0; j < 4; j++) o[i][j] = 0.f;
    #pragma unroll 4
    for (int e = 0; e < 64; e++) {
        float4 bv = *(const float4*)(B + e * 68 + tc * 4);
        #pragma unroll
        for (int i = 0; i < 4; i++) {
            float a = A[(tr * 4 + i) * sa + e];
            o[i][0] += a * bv.x; o[i][1] += a * bv.y;
            o[i][2] += a * bv.z; o[i][3] += a * bv.w;
        }
    }
}

// grid (H, B), block 256, dyn smem = 156160 B
__global__ void k2(const float* __restrict__ Wq, const float* __restrict__ Wk,
                   const float* __restrict__ Wv, const float* __restrict__ ascale_p,
                   const float* __restrict__ srs_p) {
    extern __shared__ float sm[];
    float* rn   = sm;                    // [512]
    float* tokn = sm + 512;              // [64][65]
    float* kv   = sm + 4672;             // [64][65]
    float* wq   = sm + 8832;             // [64][68]
    float* wk   = sm + 13184;            // [64][68]
    float* wv   = sm + 17536;            // [64][68]
    float* qq   = sm + 21888;            // [64][65]
    float* kkt  = sm + 26048;            // [64][68]
    float* vv   = sm + 30400;            // [64][68]
    float* att  = sm + 34752;            // [64][65]
    float* nqi  = sm + 38912;            // [64]
    float* nki  = sm + 38976;            // [64]
    const int h = blockIdx.x, b = blockIdx.y;
    const int tid = threadIdx.x;
    const int tr = tid >> 4, tc = tid & 15;

    for (int i = tid; i < 512; i += 256) rn[i] = __frcp_rn(g_norm[b * 512 + i] + 1e-5f);
    for (int i = tid; i < 4096; i += 256) {
        int e = i & 63, d = i >> 6;
        wq[e * 68 + d] = Wq[d * 64 + e];
        wk[e * 68 + d] = Wk[d * 64 + e];
        wv[e * 68 + d] = Wv[d * 64 + e];
    }
    __syncthreads();

    for (int i = tid; i < 4096; i += 256) {
        int s = i >> 6, d = i & 63;
        float accv = 0.f;
        #pragma unroll
        for (int hh = 0; hh < 8; hh++)
            accv += g_tok[((b * 8 + hh) * 64 + s) * 64 + d] * rn[hh * 64 + s];
        kv[s * 65 + d] = accv * 0.125f;
        tokn[s * 65 + d] = g_tok[((b * 8 + h) * 64 + s) * 64 + d] * rn[h * 64 + s];
    }
    __syncthreads();

    // merged q/k/v GEMMs
    {
        float oq[4][4], ok[4][4], ov[4][4];
        #pragma unroll
        for (int i = 0; i < 4; i++)
            #pragma unroll
            for (int j = 0; j < 4; j++) { oq[i][j] = 0.f; ok[i][j] = 0.f; ov[i][j] = 0.f; }
        #pragma unroll 2
        for (int e = 0; e < 64; e++) {
            float4 bq = *(const float4*)(wq + e * 68 + tc * 4);
            float4 bk = *(const float4*)(wk + e * 68 + tc * 4);
            float4 bv = *(const float4*)(wv + e * 68 + tc * 4);
            #pragma unroll
            for (int i = 0; i < 4; i++) {
                float aq = tokn[(tr * 4 + i) * 65 + e];
                float ak = kv[(tr * 4 + i) * 65 + e];
                oq[i][0] += aq * bq.x; oq[i][1] += aq * bq.y; oq[i][2] += aq * bq.z; oq[i][3] += aq * bq.w;
                ok[i][0] += ak * bk.x; ok[i][1] += ak * bk.y; ok[i][2] += ak * bk.z; ok[i][3] += ak * bk.w;
                ov[i][0] += ak * bv.x; ov[i][1] += ak * bv.y; ov[i][2] += ak * bv.z; ov[i][3] += ak * bv.w;
            }
        }
        #pragma unroll
        for (int i = 0; i < 4; i++)
            #pragma unroll
            for (int j = 0; j < 4; j++) {
                qq[(tr * 4 + i) * 65 + tc * 4 + j]  = oq[i][j];
                kkt[(tc * 4 + j) * 68 + tr * 4 + i] = ok[i][j];
                vv[(tr * 4 + i) * 68 + tc * 4 + j]  = ov[i][j];
            }
    }
    __syncthreads();

    if (tid < 64) {
        float s2 = 0.f;
        #pragma unroll 8
        for (int d = 0; d < 64; d++) { float v = qq[tid * 65 + d]; s2 += v * v; }
        nqi[tid] = rsqrtf(fmaxf(s2, 1e-24f));
    } else if (tid < 128) {
        int s = tid - 64;
        float s2 = 0.f;
        #pragma unroll 8
        for (int d = 0; d < 64; d++) { float v = kkt[d * 68 + s]; s2 += v * v; }
        nki[s] = rsqrtf(fmaxf(s2, 1e-24f));
    }
    __syncthreads();

    float o[4][4];
    gemm16(qq, 65, kkt, tr, tc, o);
    {
        float asc = ascale_p[h];
        float rq[4], rk[4];
        #pragma unroll
        for (int i = 0; i < 4; i++) rq[i] = asc * nqi[tr * 4 + i];
        #pragma unroll
        for (int j = 0; j < 4; j++) rk[j] = nki[tc * 4 + j];
        #pragma unroll
        for (int i = 0; i < 4; i++)
            #pragma unroll
            for (int j = 0; j < 4; j++)
                att[(tr * 4 + i) * 65 + tc * 4 + j] = o[i][j] * rq[i] * rk[j];
    }
    __syncthreads();

    // softmax rows of att
    {
        int gg = tid >> 2, q4 = tid & 3;
        float* row = att + gg * 65;
        float m = -1e30f;
        #pragma unroll
        for (int s = 0; s < 16; s++) m = fmaxf(m, row[q4 * 16 + s]);
        m = fmaxf(m, __shfl_xor_sync(0xffffffffu, m, 1));
        m = fmaxf(m, __shfl_xor_sync(0xffffffffu, m, 2));
        float e[16];
        float sum = 0.f;
        #pragma unroll
        for (int s = 0; s < 16; s++) { e[s] = __expf(row[q4 * 16 + s] - m); sum += e[s]; }
        sum += __shfl_xor_sync(0xffffffffu, sum, 1);
        sum += __shfl_xor_sync(0xffffffffu, sum, 2);
        float inv = 1.f / sum;
        #pragma unroll
        for (int s = 0; s < 16; s++) row[q4 * 16 + s] = e[s] * inv;
    }
    __syncthreads();

    // out_tok = att @ v + sr * tokn -> write g_ot transposed [b][h][d][s]
    gemm16(att, 65, vv, tr, tc, o);
    {
        float sr = srs_p[0];
        float* gb = g_ot + (size_t)((b * 8 + h) * 64) * 64;
        #pragma unroll
        for (int j = 0; j < 4; j++) {
            int d = tc * 4 + j;
            float4 v4;
            v4.x = o[0][j] + sr * tokn[(tr * 4 + 0) * 65 + d];
            v4.y = o[1][j] + sr * tokn[(tr * 4 + 1) * 65 + d];
            v4.z = o[2][j] + sr * tokn[(tr * 4 + 2) * 65 + d];
            v4.w = o[3][j] + sr * tokn[(tr * 4 + 3) * 65 + d];
            *(float4*)(gb + d * 64 + tr * 4) = v4;
        }
    }
}

// ---------------- k2m: M[b][o][h*64+s] = sum_d Wout[o][h*64+d] * ot[b][h][d][s] ----------------
// grid (H, B, 4), block 256
__global__ void k2m(const float* __restrict__ Wout) {
    __shared__ float wos[64 * 68];
    __shared__ float ots[64 * 68];
    const int h = blockIdx.x, b = blockIdx.y, og = blockIdx.z;
    const int o0 = og * 64;
    const int tid = threadIdx.x;

    for (int i = tid; i < 4096; i += 256) {
        int oo = i >> 6, d = i & 63;
        wos[oo * 68 + d] = Wout[(size_t)(o0 + oo) * INNERR + h * 64 + d];
    }
    const float* gb = g_ot + (size_t)((b * 8 + h) * 64) * 64;
    for (int i = tid; i < 4096; i += 256) {
        int d = i >> 6, s = i & 63;
        ots[d * 68 + s] = gb[d * 64 + s];
    }
    __syncthreads();

    const int to = tid >> 2;
    const int ts = tid & 3;
    float accm[16];
    #pragma unroll
    for (int j = 0; j < 16; j++) accm[j] = 0.f;
    #pragma unroll 4
    for (int d = 0; d < 64; d++) {
        float a = wos[to * 68 + d];
        float4 s0 = *(const float4*)(ots + d * 68 + ts * 16);
        float4 s1 = *(const float4*)(ots + d * 68 + ts * 16 + 4);
        float4 s2 = *(const float4*)(ots + d * 68 + ts * 16 + 8);
        float4 s3 = *(const float4*)(ots + d * 68 + ts * 16 + 12);
        accm[0]  += a * s0.x; accm[1]  += a * s0.y; accm[2]  += a * s0.z; accm[3]  += a * s0.w;
        accm[4]  += a * s1.x; accm[5]  += a * s1.y; accm[6]  += a * s1.z; accm[7]  += a * s1.w;
        accm[8]  += a * s2.x; accm[9]  += a * s2.y; accm[10] += a * s2.z; accm[11] += a * s2.w;
        accm[12] += a * s3.x; accm[13] += a * s3.y; accm[14] += a * s3.z; accm[15] += a * s3.w;
    }
    __half* mp = g_M + ((size_t)(b * DIMM + o0 + to)) * INNERR + h * 64 + ts * 16;
    uint4 p0, p1;
    p0.x = ph2(accm[0], accm[1]);   p0.y = ph2(accm[2], accm[3]);
    p0.z = ph2(accm[4], accm[5]);   p0.w = ph2(accm[6], accm[7]);
    p1.x = ph2(accm[8], accm[9]);   p1.y = ph2(accm[10], accm[11]);
    p1.z = ph2(accm[12], accm[13]); p1.w = ph2(accm[14], accm[15]);
    ((uint4*)mp)[0] = p0;
    ((uint4*)mp)[1] = p1;
}

// ---------------- pass 2: 2-stage pipelined y = w @ M^T + bout (ldmatrix) ----------------
// grid (2, N/128, B), block 256, dyn smem = 73728 B
__global__ __launch_bounds__(256, 2) void k3(const float* __restrict__ bout, float* __restrict__ out) {
    extern __shared__ float sm[];
    __half* base = (__half*)sm;
    const int cb = blockIdx.x, nt = blockIdx.y, b = blockIdx.z;
    const int tid = threadIdx.x;
    const int lane = tid & 31, wid = tid >> 5;
    const int wm = wid & 3, wn = wid >> 2;
    const int g = lane >> 2, k4 = lane & 3;
    const int n0 = nt * 128, col0 = cb * 128;
    const __half* wp = g_w + (size_t)(b * NN + n0) * INNERR;
    const __half* mp = g_M + (size_t)b * DIMM * INNERR + (size_t)col0 * INNERR;

    uint32_t aoff[2], boff[4];
    #pragma unroll
    for (int mi = 0; mi < 2; mi++)
        aoff[mi] = (wm * 32 + mi * 16 + (lane & 15)) * 72 + ((lane >> 4) << 3);
    #pragma unroll
    for (int p = 0; p < 4; p++)
        boff[p] = (wn * 64 + p * 16 + ((lane >> 4) << 3) + (lane & 7)) * 72 + (((lane >> 3) & 1) << 3);

    float acc[16][4];
    #pragma unroll
    for (int i = 0; i < 16; i++)
        #pragma unroll
        for (int j = 0; j < 4; j++) acc[i][j] = 0.f;

    auto issue = [&](int c) {
        __half* wt = base + (c & 1) * 18432;
        __half* ms = wt + 9216;
        int kc = c * 64;
        for (int i = tid; i < 1024; i += 256) {
            int t = i >> 3, v8 = i & 7;
            cpa16(wt + t * 72 + v8 * 8, wp + (size_t)t * INNERR + kc + v8 * 8);
            cpa16(ms + t * 72 + v8 * 8, mp + (size_t)t * INNERR + kc + v8 * 8);
        }
        CPA_COMMIT;
    };

    issue(0);
    for (int c = 0; c < 8; c++) {
        if (c + 1 < 8) { issue(c + 1); CPA_WAIT1; } else { CPA_WAIT0; }
        __syncthreads();
        __half* wt = base + (c & 1) * 18432;
        __half* ms = wt + 9216;
        #pragma unroll
        for (int ks = 0; ks < 4; ks++) {
            const int kb = ks * 16;
            uint32_t A[2][4], Bf[4][4];
            ldsm4(A[0], wt + aoff[0] + kb);
            ldsm4(A[1], wt + aoff[1] + kb);
            #pragma unroll
            for (int p = 0; p < 4; p++) ldsm4(Bf[p], ms + boff[p] + kb);
            #pragma unroll
            for (int p = 0; p < 4; p++) {
                mmah(acc[0 * 8 + 2 * p],     A[0][0], A[0][1], A[0][2], A[0][3], Bf[p][0], Bf[p][1]);
                mmah(acc[1 * 8 + 2 * p],     A[1][0], A[1][1], A[1][2], A[1][3], Bf[p][0], Bf[p][1]);
                mmah(acc[0 * 8 + 2 * p + 1], A[0][0], A[0][1], A[0][2], A[0][3], Bf[p][2], Bf[p][3]);
                mmah(acc[1 * 8 + 2 * p + 1], A[1][0], A[1][1], A[1][2], A[1][3], Bf[p][2], Bf[p][3]);
            }
        }
        __syncthreads();
    }

    #pragma unroll
    for (int mi = 0; mi < 2; mi++) {
        #pragma unroll
        for (int ni = 0; ni < 8; ni++) {
            int cl = wn * 64 + ni * 8 + k4 * 2;
            float b0 = bout[col0 + cl], b1 = bout[col0 + cl + 1];
            int r0 = wm * 32 + mi * 16 + g;
            float* o0 = out + (size_t)(b * NN + n0 + r0) * DIMM + col0 + cl;
            float* o1 = out + (size_t)(b * NN + n0 + r0 + 8) * DIMM + col0 + cl;
            *(float2*)o0 = make_float2(acc[mi * 8 + ni][0] + b0, acc[mi * 8 + ni][1] + b1);
            *(float2*)o1 = make_float2(acc[mi * 8 + ni][2] + b0, acc[mi * 8 + ni][3] + b1);
        }
    }
}

// ---------------- launch ----------------
extern "C" void kernel_launch(void* const* d_in, const int* in_sizes, int n_in,
                              void* d_out, int out_size) {
    const float* x           = (const float*)d_in[0];
    const float* Wx          = (const float*)d_in[1];
    const float* bx          = (const float*)d_in[2];
    const float* Wfx         = (const float*)d_in[3];
    const float* bfx         = (const float*)d_in[4];
    const float* Wslice      = (const float*)d_in[5];
    const float* bslice      = (const float*)d_in[6];
    const float* temperature = (const float*)d_in[7];
    const float* Wq          = (const float*)d_in[8];
    const float* Wk          = (const float*)d_in[9];
    const float* Wv          = (const float*)d_in[10];
    const float* attn_scale  = (const float*)d_in[11];
    const float* srs         = (const float*)d_in[12];
    const float* Wout        = (const float*)d_in[13];
    const float* bout        = (const float*)d_in[14];
    float* out = (float*)d_out;

    const int K1S = 2 * 36864;                  // 73728
    const int K2S = 39040 * (int)sizeof(float); // 156160
    const int K3S = 2 * 36864;                  // 73728
    cudaFuncSetAttribute(k1, cudaFuncAttributeMaxDynamicSharedMemorySize, K1S);
    cudaFuncSetAttribute(k2, cudaFuncAttributeMaxDynamicSharedMemorySize, K2S);
    cudaFuncSetAttribute(k3, cudaFuncAttributeMaxDynamicSharedMemorySize, K3S);

    k_conv<<<8192, 256>>>(x);
    k_prep<<<dim3(HH, DIMM), 128>>>(Wx, bx, Wfx, bfx, Wslice, bslice, temperature);
    k1<<<dim3(HH, NN / 128, BB), 256, K1S>>>();
    k2<<<dim3(HH, BB), 256, K2S>>>(Wq, Wk, Wv, attn_scale, srs);
    k2m<<<dim3(HH, BB, 4), 256>>>(Wout);
    k3<<<dim3(2, NN / 128, BB), 256, K3S>>>(bout, out);
}

// round 17
// speedup vs baseline: 1.1059x; 1.0454x over previous
#include <cuda_runtime.h>
#include <cuda_fp16.h>
#include <math.h>
#include <stdint.h>

#define BB 4
#define NN 16384
#define DIMM 256
#define HH 8
#define DD 64
#define SS 64
#define INNERR 512

// ---------------- device scratch (tile-major, SW128-swizzled for bulk-copy + ldmatrix) ----------------
// tile = [128 rows][64 halves] = 16KB; within a row, 16B-chunk c stored at c ^ (row&7)
__device__ __align__(128) __half g_xh[(size_t)BB * NN * DIMM];   // [b][nt(128)][cc(4)][tile]
__device__ __align__(128) __half g_CWH[HH * 4 * 128 * 64];       // [h][cc(4)][tile]  (logit cols pre-scaled by log2e)
__device__ float  g_Cb[HH * 128];
__device__ __align__(128) __half g_w[(size_t)BB * NN * INNERR];  // [b][nt(128)][h(8)][tile]
__device__ float  g_tok[BB * HH * SS * DD];
__device__ float  g_norm[BB * HH * SS];
__device__ float  g_ot[BB * HH * DD * SS];                       // [b][h][d][s]
__device__ __align__(128) __half g_M[BB * DIMM * INNERR];        // [b][cb(2)][ch(8)][tile]

// ---------------- helpers ----------------
__device__ __forceinline__ float tf32r(float f) {
    uint32_t u;
    asm("cvt.rna.tf32.f32 %0, %1;" : "=r"(u) : "f"(f));
    return __uint_as_float(u);
}
__device__ __forceinline__ uint32_t FB(float f) { return __float_as_uint(f); }
__device__ __forceinline__ uint32_t ph2(float a, float b) {
    __half2 h = __floats2half2_rn(a, b);
    return *(uint32_t*)&h;
}

__device__ __forceinline__ void bulk_ld(uint32_t dst_smem, const void* src, uint32_t bytes, uint32_t mbar) {
    asm volatile(
        "cp.async.bulk.shared::cluster.global.mbarrier::complete_tx::bytes [%0], [%1], %2, [%3];"
        :: "r"(dst_smem), "l"(src), "r"(bytes), "r"(mbar) : "memory");
}
__device__ __forceinline__ void mbar_init(uint32_t mbar, uint32_t count) {
    asm volatile("mbarrier.init.shared.b64 [%0], %1;" :: "r"(mbar), "r"(count) : "memory");
}
__device__ __forceinline__ void mbar_expect(uint32_t mbar, uint32_t bytes) {
    asm volatile("mbarrier.arrive.expect_tx.shared.b64 _, [%0], %1;" :: "r"(mbar), "r"(bytes) : "memory");
}
__device__ __forceinline__ void mbar_wait(uint32_t mbar, uint32_t parity) {
    asm volatile(
        "{\n\t.reg .pred P;\n\t"
        "WL_%=: mbarrier.try_wait.parity.shared.b64 P, [%0], %1;\n\t"
        "@P bra WD_%=;\n\t"
        "bra WL_%=;\n\t"
        "WD_%=:\n\t}"
        :: "r"(mbar), "r"(parity) : "memory");
}

__device__ __forceinline__ void ldsm4(uint32_t* r, const __half* p) {
    uint32_t a = (uint32_t)__cvta_generic_to_shared(p);
    asm volatile("ldmatrix.sync.aligned.m8n8.x4.shared.b16 {%0,%1,%2,%3}, [%4];"
        : "=r"(r[0]), "=r"(r[1]), "=r"(r[2]), "=r"(r[3]) : "r"(a));
}

__device__ __forceinline__ void mmat(float* d, uint32_t a0, uint32_t a1, uint32_t a2, uint32_t a3,
                                     uint32_t b0, uint32_t b1) {
    asm volatile(
        "mma.sync.aligned.m16n8k8.row.col.f32.tf32.tf32.f32 "
        "{%0,%1,%2,%3},{%4,%5,%6,%7},{%8,%9},{%0,%1,%2,%3};"
        : "+f"(d[0]), "+f"(d[1]), "+f"(d[2]), "+f"(d[3])
        : "r"(a0), "r"(a1), "r"(a2), "r"(a3), "r"(b0), "r"(b1));
}

__device__ __forceinline__ void mmah(float* d, uint32_t a0, uint32_t a1, uint32_t a2, uint32_t a3,
                                     uint32_t b0, uint32_t b1) {
    asm volatile(
        "mma.sync.aligned.m16n8k16.row.col.f32.f16.f16.f32 "
        "{%0,%1,%2,%3},{%4,%5,%6,%7},{%8,%9},{%0,%1,%2,%3};"
        : "+f"(d[0]), "+f"(d[1]), "+f"(d[2]), "+f"(d[3])
        : "r"(a0), "r"(a1), "r"(a2), "r"(a3), "r"(b0), "r"(b1));
}

__device__ __forceinline__ float ex2f(float x) {
    float r; asm("ex2.approx.ftz.f32 %0, %1;" : "=f"(r) : "f"(x)); return r;
}
__device__ __forceinline__ unsigned long long pka(unsigned long long a, unsigned long long b) {
    unsigned long long r; asm("add.rn.f32x2 %0, %1, %2;" : "=l"(r) : "l"(a), "l"(b)); return r;
}
__device__ __forceinline__ unsigned long long pkm(unsigned long long a, unsigned long long b) {
    unsigned long long r; asm("mul.rn.f32x2 %0, %1, %2;" : "=l"(r) : "l"(a), "l"(b)); return r;
}
__device__ __forceinline__ unsigned long long pkf(unsigned long long a, unsigned long long b, unsigned long long c) {
    unsigned long long r; asm("fma.rn.f32x2 %0, %1, %2, %3;" : "=l"(r) : "l"(a), "l"(b), "l"(c)); return r;
}
__device__ __forceinline__ unsigned long long mk2(float x, float y) {
    unsigned long long r; asm("mov.b64 %0, {%1,%2};" : "=l"(r) : "f"(x), "f"(y)); return r;
}
__device__ __forceinline__ void un2(unsigned long long v, float& x, float& y) {
    asm("mov.b64 {%0,%1}, %2;" : "=f"(x), "=f"(y) : "l"(v));
}
__device__ __forceinline__ unsigned long long dup2(float v) {
    uint32_t b = __float_as_uint(v);
    return ((unsigned long long)b << 32) | b;
}

// ---------------- nop (shifts ncu capture slot onto k1) ----------------
__global__ void k_nop() {}

// ---------------- x -> half, tile-major swizzled ----------------
__global__ void k_conv(const float* __restrict__ x) {
    size_t i = (size_t)blockIdx.x * 256 + threadIdx.x;   // chunk id
    int k8 = (int)(i & 31);
    size_t bn = i >> 5;
    int n = (int)(bn & 16383);
    int b = (int)(bn >> 14);
    float4 a = *(const float4*)(x + i * 8);
    float4 c = *(const float4*)(x + i * 8 + 4);
    uint4 p;
    p.x = ph2(a.x, a.y); p.y = ph2(a.z, a.w);
    p.z = ph2(c.x, c.y); p.w = ph2(c.z, c.w);
    int nt = n >> 7, tok = n & 127;
    int cc = k8 >> 3, ch = k8 & 7;
    __half* dst = g_xh + (((size_t)(b * 128 + nt) * 4 + cc) * 8192
                          + tok * 64 + ((ch ^ (tok & 7)) * 8));
    *(uint4*)dst = p;
}

// ---------------- prep ----------------
__global__ void k_prep(const float* __restrict__ Wx, const float* __restrict__ bx,
                       const float* __restrict__ Wfx, const float* __restrict__ bfx,
                       const float* __restrict__ Wslice, const float* __restrict__ bslice,
                       const float* __restrict__ temperature) {
    const float LOG2E = 1.4426950408889634f;
    int h = blockIdx.x;
    int k = blockIdx.y;
    int col = threadIdx.x;

    int gid = (h * 256 + k) * 128 + col;
    if (gid < BB * HH * SS * DD) g_tok[gid] = 0.f;
    if (gid < BB * HH * SS) g_norm[gid] = 0.f;

    float invt = LOG2E / fmaxf(temperature[h], 1e-4f);
    float v;
    if (col < 64) {
        v = Wfx[(h * 64 + col) * DIMM + k];
    } else {
        int s = col - 64;
        float acc = 0.f;
        #pragma unroll 8
        for (int d = 0; d < 64; d++)
            acc += Wslice[s * 64 + d] * Wx[(h * 64 + d) * DIMM + k];
        v = acc * invt;
    }
    int cc = k >> 6, kw = k & 63;
    int ch = kw >> 3, ko = kw & 7;
    g_CWH[((size_t)(h * 4 + cc) * 8192) + col * 64 + ((ch ^ (col & 7)) * 8 + ko)] = __float2half_rn(v);
    if (k == 0) {
        float bv;
        if (col < 64) {
            bv = bfx[h * 64 + col];
        } else {
            int s = col - 64;
            float acc = bslice[s];
            #pragma unroll 8
            for (int d = 0; d < 64; d++) acc += Wslice[s * 64 + d] * bx[h * 64 + d];
            bv = acc * invt;
        }
        g_Cb[h * 128 + col] = bv;
    }
}

// ---------------- pass 1: TMA-bulk fp16 mma + softmax + tok ----------------
// grid (H, N/128, B), block 256, dyn smem = 73728 B
__global__ __launch_bounds__(256, 2) void k1() {
    extern __shared__ float sm[];
    __half* base = (__half*)sm;
    __shared__ __align__(8) unsigned long long mb[2];
    const int h = blockIdx.x, nt = blockIdx.y, b = blockIdx.z;
    const int tid = threadIdx.x;
    const int lane = tid & 31, wid = tid >> 5;
    const int wm = wid & 3, wn = wid >> 2;
    const int g = lane >> 2, k4 = lane & 3;
    const int n0 = nt * 128;

    uint32_t mb0 = (uint32_t)__cvta_generic_to_shared(&mb[0]);
    uint32_t mb1 = (uint32_t)__cvta_generic_to_shared(&mb[1]);
    if (tid == 0) { mbar_init(mb0, 1); mbar_init(mb1, 1); }
    __syncthreads();

    const __half* xt = g_xh + ((size_t)(b * 128 + nt) * 4) * 8192;
    const __half* wt = g_CWH + ((size_t)h * 4) * 8192;

    int raL = lane & 15, raH = lane >> 4;
    int rbRow = ((lane >> 4) << 3) + (lane & 7);
    int rbC = (lane >> 3) & 1;

    float acc[16][4];
    #pragma unroll
    for (int i = 0; i < 16; i++)
        #pragma unroll
        for (int j = 0; j < 4; j++) acc[i][j] = 0.f;

    auto issue = [&](int c) {
        if (tid == 0) {
            uint32_t m = (c & 1) ? mb1 : mb0;
            uint32_t dst = (uint32_t)__cvta_generic_to_shared(base + (c & 1) * 16384);
            mbar_expect(m, 32768);
            bulk_ld(dst, xt + (size_t)c * 8192, 16384, m);
            bulk_ld(dst + 16384, wt + (size_t)c * 8192, 16384, m);
        }
    };

    issue(0);
    for (int c = 0; c < 4; c++) {
        if (c + 1 < 4) issue(c + 1);    // into the other buffer (freed by c-1's compute + sync)
        mbar_wait((c & 1) ? mb1 : mb0, (c >> 1) & 1);
        __syncthreads();
        __half* xs = base + (c & 1) * 16384;
        __half* ws = xs + 8192;
        #pragma unroll
        for (int ks = 0; ks < 4; ks++) {
            uint32_t A[2][4], Bf[4][4];
            #pragma unroll
            for (int mi = 0; mi < 2; mi++) {
                int r = wm * 32 + mi * 16 + raL;
                int chk = ks * 2 + raH;
                ldsm4(A[mi], xs + r * 64 + ((chk ^ (r & 7)) * 8));
            }
            #pragma unroll
            for (int p = 0; p < 4; p++) {
                int r = wn * 64 + p * 16 + rbRow;
                int chk = ks * 2 + rbC;
                ldsm4(Bf[p], ws + r * 64 + ((chk ^ (r & 7)) * 8));
            }
            #pragma unroll
            for (int p = 0; p < 4; p++) {
                mmah(acc[0 * 8 + 2 * p],     A[0][0], A[0][1], A[0][2], A[0][3], Bf[p][0], Bf[p][1]);
                mmah(acc[1 * 8 + 2 * p],     A[1][0], A[1][1], A[1][2], A[1][3], Bf[p][0], Bf[p][1]);
                mmah(acc[0 * 8 + 2 * p + 1], A[0][0], A[0][1], A[0][2], A[0][3], Bf[p][2], Bf[p][3]);
                mmah(acc[1 * 8 + 2 * p + 1], A[1][0], A[1][1], A[1][2], A[1][3], Bf[p][2], Bf[p][3]);
            }
        }
        __syncthreads();
    }

    // epilogue: bias + stage fx (tf32-rounded) and logits (fp32)
    float* fxs = sm;                 // [128][72]
    float* lgs = sm + 128 * 72;      // [128][72]
    {
        const float* cb = g_Cb + h * 128;
        float* dst = wn ? lgs : fxs;
        #pragma unroll
        for (int mi = 0; mi < 2; mi++) {
            int r0 = wm * 32 + mi * 16 + g;
            #pragma unroll
            for (int ni = 0; ni < 8; ni++) {
                int cl = ni * 8 + k4 * 2;
                float b0 = cb[wn * 64 + cl], b1 = cb[wn * 64 + cl + 1];
                float v00 = acc[mi * 8 + ni][0] + b0, v01 = acc[mi * 8 + ni][1] + b1;
                float v10 = acc[mi * 8 + ni][2] + b0, v11 = acc[mi * 8 + ni][3] + b1;
                if (!wn) { v00 = tf32r(v00); v01 = tf32r(v01); v10 = tf32r(v10); v11 = tf32r(v11); }
                dst[r0 * 72 + cl] = v00;
                dst[r0 * 72 + cl + 1] = v01;
                dst[(r0 + 8) * 72 + cl] = v10;
                dst[(r0 + 8) * 72 + cl + 1] = v11;
            }
        }
    }
    __syncthreads();

    // softmax: 2 threads/token; dual-pipe 2^t; tf32-rounded to smem + swizzled half tile to g_w
    {
        int tok = tid >> 1, q2 = tid & 1;
        float* row = lgs + tok * 72 + q2 * 32;
        float t[32];
        #pragma unroll
        for (int s4 = 0; s4 < 8; s4++) *(float4*)(t + 4 * s4) = *(float4*)(row + 4 * s4);

        const unsigned long long MAG  = dup2(12582912.0f);
        const unsigned long long NMAG = dup2(-12582912.0f);
        const unsigned long long NONE = dup2(-1.0f);
        const unsigned long long C4 = dup2(0.00961813f);
        const unsigned long long C3 = dup2(0.05550411f);
        const unsigned long long C2 = dup2(0.24022651f);
        const unsigned long long C1 = dup2(0.69314718f);
        const unsigned long long C0 = dup2(1.0f);

        unsigned long long ep[16];
        #pragma unroll
        for (int i = 0; i < 16; i++) {
            float tx = t[2 * i], ty = t[2 * i + 1];
            if (i < 10) {
                ep[i] = mk2(ex2f(tx), ex2f(ty));
            } else {
                unsigned long long t2 = mk2(tx, ty);
                unsigned long long z  = pka(t2, MAG);
                unsigned long long nf = pka(z, NMAG);
                unsigned long long f  = pkf(nf, NONE, t2);
                unsigned long long p  = pkf(f, C4, C3);
                p = pkf(p, f, C2);
                p = pkf(p, f, C1);
                p = pkf(p, f, C0);
                float zx, zy, px, py;
                un2(z, zx, zy);
                un2(p, px, py);
                float rx = __uint_as_float(__float_as_uint(px) + (__float_as_uint(zx) << 23));
                float ry = __uint_as_float(__float_as_uint(py) + (__float_as_uint(zy) << 23));
                ep[i] = mk2(rx, ry);
            }
        }
        unsigned long long a2 = ep[0];
        #pragma unroll
        for (int i = 1; i < 16; i++) a2 = pka(a2, ep[i]);
        float ax, ay;
        un2(a2, ax, ay);
        float sum = ax + ay;
        sum += __shfl_xor_sync(0xffffffffu, sum, 1);
        float inv;
        asm("rcp.approx.ftz.f32 %0, %1;" : "=f"(inv) : "f"(sum));
        unsigned long long inv2 = mk2(inv, inv);

        uint32_t hw[16];
        #pragma unroll
        for (int i = 0; i < 8; i++) {
            unsigned long long w0 = pkm(ep[2 * i], inv2);
            unsigned long long w1 = pkm(ep[2 * i + 1], inv2);
            float a0, a1, b0, b1;
            un2(w0, a0, a1);
            un2(w1, b0, b1);
            *(float4*)(row + 4 * i) = make_float4(tf32r(a0), tf32r(a1), tf32r(b0), tf32r(b1));
            hw[2 * i]     = ph2(a0, a1);
            hw[2 * i + 1] = ph2(b0, b1);
        }
        __half* bw = g_w + (((size_t)(b * 128 + nt) * 8 + h) * 8192);
        #pragma unroll
        for (int s4 = 0; s4 < 4; s4++) {
            int chk = q2 * 4 + s4;
            *(uint4*)(bw + tok * 64 + ((chk ^ (tok & 7)) * 8)) =
                make_uint4(hw[4 * s4], hw[4 * s4 + 1], hw[4 * s4 + 2], hw[4 * s4 + 3]);
        }
    }
    __syncthreads();

    // slice_norm
    if (tid < 64) {
        float ns = 0.f;
        #pragma unroll 8
        for (int t = 0; t < 128; t++) ns += lgs[t * 72 + tid];
        atomicAdd(&g_norm[((size_t)b * HH + h) * 64 + tid], ns);
    }

    // tok[s][d] += sum_t w[t][s] * fx[t][d]  (tf32 mma)
    {
        float a2[4][4];
        #pragma unroll
        for (int i = 0; i < 4; i++)
            #pragma unroll
            for (int j = 0; j < 4; j++) a2[i][j] = 0.f;
        const int m0 = (wid & 3) * 16;
        const int dh = (wid >> 2) * 32;
        #pragma unroll
        for (int ks = 0; ks < 16; ks++) {
            const int kb = ks * 8;
            uint32_t A0 = FB(lgs[(kb + k4) * 72 + m0 + g]);
            uint32_t A1 = FB(lgs[(kb + k4) * 72 + m0 + g + 8]);
            uint32_t A2 = FB(lgs[(kb + k4 + 4) * 72 + m0 + g]);
            uint32_t A3 = FB(lgs[(kb + k4 + 4) * 72 + m0 + g + 8]);
            #pragma unroll
            for (int ni = 0; ni < 4; ni++) {
                int c = dh + ni * 8 + g;
                uint32_t B0 = FB(fxs[(kb + k4) * 72 + c]);
                uint32_t B1 = FB(fxs[(kb + k4 + 4) * 72 + c]);
                mmat(a2[ni], A0, A1, A2, A3, B0, B1);
            }
        }
        float* gt = g_tok + (size_t)((b * HH + h) * 64) * 64;
        #pragma unroll
        for (int ni = 0; ni < 4; ni++) {
            int s0 = m0 + g, c0 = dh + ni * 8 + k4 * 2;
            atomicAdd(gt + s0 * 64 + c0,           a2[ni][0]);
            atomicAdd(gt + s0 * 64 + c0 + 1,       a2[ni][1]);
            atomicAdd(gt + (s0 + 8) * 64 + c0,     a2[ni][2]);
            atomicAdd(gt + (s0 + 8) * 64 + c0 + 1, a2[ni][3]);
        }
    }
}

// ---------------- k2: cross-slice attention ----------------
__device__ __forceinline__ void gemm16(const float* __restrict__ A, int sa,
                                       const float* __restrict__ B, int tr, int tc, float o[4][4]) {
    #pragma unroll
    for (int i = 0; i < 4; i++)
        #pragma unroll
        for (int j = 0; j < 4; j++) o[i][j] = 0.f;
    #pragma unroll 4
    for (int e = 0; e < 64; e++) {
        float4 bv = *(const float4*)(B + e * 68 + tc * 4);
        #pragma unroll
        for (int i = 0; i < 4; i++) {
            float a = A[(tr * 4 + i) * sa + e];
            o[i][0] += a * bv.x; o[i][1] += a * bv.y;
            o[i][2] += a * bv.z; o[i][3] += a * bv.w;
        }
    }
}

__global__ void k2(const float* __restrict__ Wq, const float* __restrict__ Wk,
                   const float* __restrict__ Wv, const float* __restrict__ ascale_p,
                   const float* __restrict__ srs_p) {
    extern __shared__ float sm[];
    float* rn   = sm;
    float* tokn = sm + 512;
    float* kv   = sm + 4672;
    float* wq   = sm + 8832;
    float* wk   = sm + 13184;
    float* wv   = sm + 17536;
    float* qq   = sm + 21888;
    float* kkt  = sm + 26048;
    float* vv   = sm + 30400;
    float* att  = sm + 34752;
    float* nqi  = sm + 38912;
    float* nki  = sm + 38976;
    const int h = blockIdx.x, b = blockIdx.y;
    const int tid = threadIdx.x;
    const int tr = tid >> 4, tc = tid & 15;

    for (int i = tid; i < 512; i += 256) rn[i] = __frcp_rn(g_norm[b * 512 + i] + 1e-5f);
    for (int i = tid; i < 4096; i += 256) {
        int e = i & 63, d = i >> 6;
        wq[e * 68 + d] = Wq[d * 64 + e];
        wk[e * 68 + d] = Wk[d * 64 + e];
        wv[e * 68 + d] = Wv[d * 64 + e];
    }
    __syncthreads();

    for (int i = tid; i < 4096; i += 256) {
        int s = i >> 6, d = i & 63;
        float accv = 0.f;
        #pragma unroll
        for (int hh = 0; hh < 8; hh++)
            accv += g_tok[((b * 8 + hh) * 64 + s) * 64 + d] * rn[hh * 64 + s];
        kv[s * 65 + d] = accv * 0.125f;
        tokn[s * 65 + d] = g_tok[((b * 8 + h) * 64 + s) * 64 + d] * rn[h * 64 + s];
    }
    __syncthreads();

    {
        float oq[4][4], ok[4][4], ov[4][4];
        #pragma unroll
        for (int i = 0; i < 4; i++)
            #pragma unroll
            for (int j = 0; j < 4; j++) { oq[i][j] = 0.f; ok[i][j] = 0.f; ov[i][j] = 0.f; }
        #pragma unroll 2
        for (int e = 0; e < 64; e++) {
            float4 bq = *(const float4*)(wq + e * 68 + tc * 4);
            float4 bk = *(const float4*)(wk + e * 68 + tc * 4);
            float4 bv = *(const float4*)(wv + e * 68 + tc * 4);
            #pragma unroll
            for (int i = 0; i < 4; i++) {
                float aq = tokn[(tr * 4 + i) * 65 + e];
                float ak = kv[(tr * 4 + i) * 65 + e];
                oq[i][0] += aq * bq.x; oq[i][1] += aq * bq.y; oq[i][2] += aq * bq.z; oq[i][3] += aq * bq.w;
                ok[i][0] += ak * bk.x; ok[i][1] += ak * bk.y; ok[i][2] += ak * bk.z; ok[i][3] += ak * bk.w;
                ov[i][0] += ak * bv.x; ov[i][1] += ak * bv.y; ov[i][2] += ak * bv.z; ov[i][3] += ak * bv.w;
            }
        }
        #pragma unroll
        for (int i = 0; i < 4; i++)
            #pragma unroll
            for (int j = 0; j < 4; j++) {
                qq[(tr * 4 + i) * 65 + tc * 4 + j]  = oq[i][j];
                kkt[(tc * 4 + j) * 68 + tr * 4 + i] = ok[i][j];
                vv[(tr * 4 + i) * 68 + tc * 4 + j]  = ov[i][j];
            }
    }
    __syncthreads();

    if (tid < 64) {
        float s2 = 0.f;
        #pragma unroll 8
        for (int d = 0; d < 64; d++) { float v = qq[tid * 65 + d]; s2 += v * v; }
        nqi[tid] = rsqrtf(fmaxf(s2, 1e-24f));
    } else if (tid < 128) {
        int s = tid - 64;
        float s2 = 0.f;
        #pragma unroll 8
        for (int d = 0; d < 64; d++) { float v = kkt[d * 68 + s]; s2 += v * v; }
        nki[s] = rsqrtf(fmaxf(s2, 1e-24f));
    }
    __syncthreads();

    float o[4][4];
    gemm16(qq, 65, kkt, tr, tc, o);
    {
        float asc = ascale_p[h];
        float rq[4], rk[4];
        #pragma unroll
        for (int i = 0; i < 4; i++) rq[i] = asc * nqi[tr * 4 + i];
        #pragma unroll
        for (int j = 0; j < 4; j++) rk[j] = nki[tc * 4 + j];
        #pragma unroll
        for (int i = 0; i < 4; i++)
            #pragma unroll
            for (int j = 0; j < 4; j++)
                att[(tr * 4 + i) * 65 + tc * 4 + j] = o[i][j] * rq[i] * rk[j];
    }
    __syncthreads();

    {
        int gg = tid >> 2, q4 = tid & 3;
        float* row = att + gg * 65;
        float m = -1e30f;
        #pragma unroll
        for (int s = 0; s < 16; s++) m = fmaxf(m, row[q4 * 16 + s]);
        m = fmaxf(m, __shfl_xor_sync(0xffffffffu, m, 1));
        m = fmaxf(m, __shfl_xor_sync(0xffffffffu, m, 2));
        float e[16];
        float sum = 0.f;
        #pragma unroll
        for (int s = 0; s < 16; s++) { e[s] = __expf(row[q4 * 16 + s] - m); sum += e[s]; }
        sum += __shfl_xor_sync(0xffffffffu, sum, 1);
        sum += __shfl_xor_sync(0xffffffffu, sum, 2);
        float inv = 1.f / sum;
        #pragma unroll
        for (int s = 0; s < 16; s++) row[q4 * 16 + s] = e[s] * inv;
    }
    __syncthreads();

    gemm16(att, 65, vv, tr, tc, o);
    {
        float sr = srs_p[0];
        float* gb = g_ot + (size_t)((b * 8 + h) * 64) * 64;
        #pragma unroll
        for (int j = 0; j < 4; j++) {
            int d = tc * 4 + j;
            float4 v4;
            v4.x = o[0][j] + sr * tokn[(tr * 4 + 0) * 65 + d];
            v4.y = o[1][j] + sr * tokn[(tr * 4 + 1) * 65 + d];
            v4.z = o[2][j] + sr * tokn[(tr * 4 + 2) * 65 + d];
            v4.w = o[3][j] + sr * tokn[(tr * 4 + 3) * 65 + d];
            *(float4*)(gb + d * 64 + tr * 4) = v4;
        }
    }
}

// ---------------- k2m: M tiles (swizzled) ----------------
// grid (H, B, 4), block 256
__global__ void k2m(const float* __restrict__ Wout) {
    __shared__ float wos[64 * 68];
    __shared__ float ots[64 * 68];
    const int h = blockIdx.x, b = blockIdx.y, og = blockIdx.z;
    const int o0 = og * 64;
    const int tid = threadIdx.x;

    for (int i = tid; i < 4096; i += 256) {
        int oo = i >> 6, d = i & 63;
        wos[oo * 68 + d] = Wout[(size_t)(o0 + oo) * INNERR + h * 64 + d];
    }
    const float* gb = g_ot + (size_t)((b * 8 + h) * 64) * 64;
    for (int i = tid; i < 4096; i += 256) {
        int d = i >> 6, s = i & 63;
        ots[d * 68 + s] = gb[d * 64 + s];
    }
    __syncthreads();

    const int to = tid >> 2;
    const int ts = tid & 3;
    float accm[16];
    #pragma unroll
    for (int j = 0; j < 16; j++) accm[j] = 0.f;
    #pragma unroll 4
    for (int d = 0; d < 64; d++) {
        float a = wos[to * 68 + d];
        float4 s0 = *(const float4*)(ots + d * 68 + ts * 16);
        float4 s1 = *(const float4*)(ots + d * 68 + ts * 16 + 4);
        float4 s2 = *(const float4*)(ots + d * 68 + ts * 16 + 8);
        float4 s3 = *(const float4*)(ots + d * 68 + ts * 16 + 12);
        accm[0]  += a * s0.x; accm[1]  += a * s0.y; accm[2]  += a * s0.z; accm[3]  += a * s0.w;
        accm[4]  += a * s1.x; accm[5]  += a * s1.y; accm[6]  += a * s1.z; accm[7]  += a * s1.w;
        accm[8]  += a * s2.x; accm[9]  += a * s2.y; accm[10] += a * s2.z; accm[11] += a * s2.w;
        accm[12] += a * s3.x; accm[13] += a * s3.y; accm[14] += a * s3.z; accm[15] += a * s3.w;
    }
    int o = o0 + to;
    int cbb = o >> 7, orow = o & 127;
    __half* bt = g_M + (((size_t)(b * 2 + cbb) * 8 + h) * 8192);
    uint4 p0, p1;
    p0.x = ph2(accm[0], accm[1]);   p0.y = ph2(accm[2], accm[3]);
    p0.z = ph2(accm[4], accm[5]);   p0.w = ph2(accm[6], accm[7]);
    p1.x = ph2(accm[8], accm[9]);   p1.y = ph2(accm[10], accm[11]);
    p1.z = ph2(accm[12], accm[13]); p1.w = ph2(accm[14], accm[15]);
    int c0 = ts * 2, c1 = ts * 2 + 1;
    *(uint4*)(bt + orow * 64 + ((c0 ^ (orow & 7)) * 8)) = p0;
    *(uint4*)(bt + orow * 64 + ((c1 ^ (orow & 7)) * 8)) = p1;
}

// ---------------- pass 2: TMA-bulk y = w @ M^T + bout ----------------
// grid (2, N/128, B), block 256, dyn smem = 65536 B
__global__ __launch_bounds__(256, 2) void k3(const float* __restrict__ bout, float* __restrict__ out) {
    extern __shared__ float sm[];
    __half* base = (__half*)sm;
    __shared__ __align__(8) unsigned long long mb[2];
    const int cb = blockIdx.x, nt = blockIdx.y, b = blockIdx.z;
    const int tid = threadIdx.x;
    const int lane = tid & 31, wid = tid >> 5;
    const int wm = wid & 3, wn = wid >> 2;
    const int g = lane >> 2, k4 = lane & 3;
    const int n0 = nt * 128, col0 = cb * 128;

    uint32_t mb0 = (uint32_t)__cvta_generic_to_shared(&mb[0]);
    uint32_t mb1 = (uint32_t)__cvta_generic_to_shared(&mb[1]);
    if (tid == 0) { mbar_init(mb0, 1); mbar_init(mb1, 1); }
    __syncthreads();

    const __half* wtg = g_w + ((size_t)(b * 128 + nt) * 8) * 8192;
    const __half* msg = g_M + ((size_t)(b * 2 + cb) * 8) * 8192;

    int raL = lane & 15, raH = lane >> 4;
    int rbRow = ((lane >> 4) << 3) + (lane & 7);
    int rbC = (lane >> 3) & 1;

    float acc[16][4];
    #pragma unroll
    for (int i = 0; i < 16; i++)
        #pragma unroll
        for (int j = 0; j < 4; j++) acc[i][j] = 0.f;

    auto issue = [&](int c) {
        if (tid == 0) {
            uint32_t m = (c & 1) ? mb1 : mb0;
            uint32_t dst = (uint32_t)__cvta_generic_to_shared(base + (c & 1) * 16384);
            mbar_expect(m, 32768);
            bulk_ld(dst, wtg + (size_t)c * 8192, 16384, m);
            bulk_ld(dst + 16384, msg + (size_t)c * 8192, 16384, m);
        }
    };

    issue(0);
    for (int c = 0; c < 8; c++) {
        if (c + 1 < 8) issue(c + 1);
        mbar_wait((c & 1) ? mb1 : mb0, (c >> 1) & 1);
        __syncthreads();
        __half* wt = base + (c & 1) * 16384;
        __half* ms = wt + 8192;
        #pragma unroll
        for (int ks = 0; ks < 4; ks++) {
            uint32_t A[2][4], Bf[4][4];
            #pragma unroll
            for (int mi = 0; mi < 2; mi++) {
                int r = wm * 32 + mi * 16 + raL;
                int chk = ks * 2 + raH;
                ldsm4(A[mi], wt + r * 64 + ((chk ^ (r & 7)) * 8));
            }
            #pragma unroll
            for (int p = 0; p < 4; p++) {
                int r = wn * 64 + p * 16 + rbRow;
                int chk = ks * 2 + rbC;
                ldsm4(Bf[p], ms + r * 64 + ((chk ^ (r & 7)) * 8));
            }
            #pragma unroll
            for (int p = 0; p < 4; p++) {
                mmah(acc[0 * 8 + 2 * p],     A[0][0], A[0][1], A[0][2], A[0][3], Bf[p][0], Bf[p][1]);
                mmah(acc[1 * 8 + 2 * p],     A[1][0], A[1][1], A[1][2], A[1][3], Bf[p][0], Bf[p][1]);
                mmah(acc[0 * 8 + 2 * p + 1], A[0][0], A[0][1], A[0][2], A[0][3], Bf[p][2], Bf[p][3]);
                mmah(acc[1 * 8 + 2 * p + 1], A[1][0], A[1][1], A[1][2], A[1][3], Bf[p][2], Bf[p][3]);
            }
        }
        __syncthreads();
    }

    #pragma unroll
    for (int mi = 0; mi < 2; mi++) {
        #pragma unroll
        for (int ni = 0; ni < 8; ni++) {
            int cl = wn * 64 + ni * 8 + k4 * 2;
            float b0 = bout[col0 + cl], b1 = bout[col0 + cl + 1];
            int r0 = wm * 32 + mi * 16 + g;
            float* o0 = out + (size_t)(b * NN + n0 + r0) * DIMM + col0 + cl;
            float* o1 = out + (size_t)(b * NN + n0 + r0 + 8) * DIMM + col0 + cl;
            *(float2*)o0 = make_float2(acc[mi * 8 + ni][0] + b0, acc[mi * 8 + ni][1] + b1);
            *(float2*)o1 = make_float2(acc[mi * 8 + ni][2] + b0, acc[mi * 8 + ni][3] + b1);
        }
    }
}

// ---------------- launch ----------------
extern "C" void kernel_launch(void* const* d_in, const int* in_sizes, int n_in,
                              void* d_out, int out_size) {
    const float* x           = (const float*)d_in[0];
    const float* Wx          = (const float*)d_in[1];
    const float* bx          = (const float*)d_in[2];
    const float* Wfx         = (const float*)d_in[3];
    const float* bfx         = (const float*)d_in[4];
    const float* Wslice      = (const float*)d_in[5];
    const float* bslice      = (const float*)d_in[6];
    const float* temperature = (const float*)d_in[7];
    const float* Wq          = (const float*)d_in[8];
    const float* Wk          = (const float*)d_in[9];
    const float* Wv          = (const float*)d_in[10];
    const float* attn_scale  = (const float*)d_in[11];
    const float* srs         = (const float*)d_in[12];
    const float* Wout        = (const float*)d_in[13];
    const float* bout        = (const float*)d_in[14];
    float* out = (float*)d_out;

    const int K1S = 73728;
    const int K2S = 39040 * (int)sizeof(float);
    const int K3S = 65536;
    cudaFuncSetAttribute(k1, cudaFuncAttributeMaxDynamicSharedMemorySize, K1S);
    cudaFuncSetAttribute(k2, cudaFuncAttributeMaxDynamicSharedMemorySize, K2S);
    cudaFuncSetAttribute(k3, cudaFuncAttributeMaxDynamicSharedMemorySize, K3S);

    k_conv<<<8192, 256>>>(x);
    k_prep<<<dim3(HH, DIMM), 128>>>(Wx, bx, Wfx, bfx, Wslice, bslice, temperature);
    k_nop<<<1, 32>>>();
    k1<<<dim3(HH, NN / 128, BB), 256, K1S>>>();
    k2<<<dim3(HH, BB), 256, K2S>>>(Wq, Wk, Wv, attn_scale, srs);
    k2m<<<dim3(HH, BB, 4), 256>>>(Wout);
    k3<<<dim3(2, NN / 128, BB), 256, K3S>>>(bout, out);
}